// round 8
// baseline (speedup 1.0000x reference)
#include <cuda_runtime.h>
#include <cuda_bf16.h>
#include <cstdint>

#define NHEADS 20
#define HEAD_DIM 64
#define HIDDEN 1280
#define CROSS 2048
#define NB 4
#define SQ 4096
#define TXT 77
#define NTOK 4
#define ENC (TXT + NTOK)

// ============================================================================
// PTX helpers (baseline-family only: mma.sync / ldmatrix / cp.async)
// ============================================================================
__device__ __forceinline__ uint32_t smem_to_u32(const void* smem_ptr) {
    uint32_t addr;
    asm("{ .reg .u64 tmp; cvta.to.shared.u64 tmp, %1; cvt.u32.u64 %0, tmp; }"
        : "=r"(addr) : "l"(smem_ptr));
    return addr;
}

__device__ __forceinline__ void cp_async16(uint32_t dst, const void* src, int bytes) {
    asm volatile("cp.async.cg.shared.global [%0], [%1], 16, %2;"
                 :: "r"(dst), "l"(src), "r"(bytes));
}
#define CP_COMMIT() asm volatile("cp.async.commit_group;" ::: "memory")
#define CP_WAIT(N)  asm volatile("cp.async.wait_group %0;" :: "n"(N) : "memory")

__device__ __forceinline__ void ldsm_x4(uint32_t* r, uint32_t a) {
    asm volatile("ldmatrix.sync.aligned.m8n8.x4.shared.b16 {%0,%1,%2,%3}, [%4];"
                 : "=r"(r[0]), "=r"(r[1]), "=r"(r[2]), "=r"(r[3]) : "r"(a));
}

__device__ __forceinline__ void ldsm_x4_t(uint32_t* r, uint32_t a) {
    asm volatile("ldmatrix.sync.aligned.m8n8.x4.trans.shared.b16 {%0,%1,%2,%3}, [%4];"
                 : "=r"(r[0]), "=r"(r[1]), "=r"(r[2]), "=r"(r[3]) : "r"(a));
}

__device__ __forceinline__ void mma16816(float* c, const uint32_t* a,
                                         uint32_t b0, uint32_t b1) {
    asm volatile(
        "mma.sync.aligned.m16n8k16.row.col.f32.bf16.bf16.f32 "
        "{%0,%1,%2,%3},{%4,%5,%6,%7},{%8,%9},{%0,%1,%2,%3};"
        : "+f"(c[0]), "+f"(c[1]), "+f"(c[2]), "+f"(c[3])
        : "r"(a[0]), "r"(a[1]), "r"(a[2]), "r"(a[3]), "r"(b0), "r"(b1));
}

__device__ __forceinline__ uint32_t pack_bf16x2(float a, float b) {
    __nv_bfloat162 t;
    t.x = __float2bfloat16(a);
    t.y = __float2bfloat16(b);
    return *reinterpret_cast<uint32_t*>(&t);
}

// ============================================================================
// Scratch (static device allocations)
// ============================================================================
#define PART_STRIDE ((long)16 * TXT * HIDDEN)   // floats per split-K partial

__device__ __nv_bfloat16 g_ahi[NB * SQ * HIDDEN];
__device__ __nv_bfloat16 g_alo[NB * SQ * HIDDEN];
__device__ __nv_bfloat16 g_qhi[NB * SQ * HIDDEN];
__device__ __nv_bfloat16 g_qlo[NB * SQ * HIDDEN];
__device__ __nv_bfloat16 g_ehi[NB * ENC * CROSS];
__device__ __nv_bfloat16 g_elo[NB * ENC * CROSS];
__device__ __nv_bfloat16 g_wqT_hi[HIDDEN * HIDDEN];
__device__ __nv_bfloat16 g_wqT_lo[HIDDEN * HIDDEN];
__device__ __nv_bfloat16 g_wT_hi[4 * HIDDEN * CROSS];
__device__ __nv_bfloat16 g_wT_lo[4 * HIDDEN * CROSS];
__device__ __nv_bfloat16 g_woutT_hi[HIDDEN * HIDDEN];
__device__ __nv_bfloat16 g_woutT_lo[HIDDEN * HIDDEN];
__device__ __nv_bfloat16 g_kvhi[4 * NB * TXT * HIDDEN];  // k,v,ipk,ipv
__device__ __nv_bfloat16 g_kvlo[4 * NB * TXT * HIDDEN];
__device__ float g_part[8 * 16 * TXT * HIDDEN];          // split-K partials

// ============================================================================
// fp32 -> bf16 hi/lo split
// ============================================================================
__global__ __launch_bounds__(256)
void split_kernel(const float* __restrict__ in, __nv_bfloat16* __restrict__ hi,
                  __nv_bfloat16* __restrict__ lo, int n4)
{
    int i = blockIdx.x * blockDim.x + threadIdx.x;
    if (i >= n4) return;
    float4 x = ((const float4*)in)[i];
    __nv_bfloat16 h0 = __float2bfloat16(x.x);
    __nv_bfloat16 h1 = __float2bfloat16(x.y);
    __nv_bfloat16 h2 = __float2bfloat16(x.z);
    __nv_bfloat16 h3 = __float2bfloat16(x.w);
    __nv_bfloat162 hA; hA.x = h0; hA.y = h1;
    __nv_bfloat162 hB; hB.x = h2; hB.y = h3;
    ((__nv_bfloat162*)hi)[2 * i]     = hA;
    ((__nv_bfloat162*)hi)[2 * i + 1] = hB;
    __nv_bfloat162 lA;
    lA.x = __float2bfloat16(x.x - __bfloat162float(h0));
    lA.y = __float2bfloat16(x.y - __bfloat162float(h1));
    __nv_bfloat162 lB;
    lB.x = __float2bfloat16(x.z - __bfloat162float(h2));
    lB.y = __float2bfloat16(x.w - __bfloat162float(h3));
    ((__nv_bfloat162*)lo)[2 * i]     = lA;
    ((__nv_bfloat162*)lo)[2 * i + 1] = lB;
}

// ============================================================================
// Merged transpose + split of all 6 weights (grid.z selects weight).
// ============================================================================
struct TSArgs {
    const float* src[6];
    __nv_bfloat16* dhi[6];
    __nv_bfloat16* dlo[6];
    int K[6];
};

__global__ __launch_bounds__(256)
void transpose_split_all(TSArgs args)
{
    const int w = blockIdx.z;
    const int K = args.K[w];
    const int k0 = blockIdx.y * 32;
    if (k0 >= K) return;
    const float* in = args.src[w];
    __nv_bfloat16* ohi = args.dhi[w];
    __nv_bfloat16* olo = args.dlo[w];

    __shared__ float t[32][33];
    const int tx = threadIdx.x, ty = threadIdx.y;
    const int n0 = blockIdx.x * 32;
    #pragma unroll
    for (int j = ty; j < 32; j += 8)
        t[j][tx] = in[(long)(k0 + j) * HIDDEN + n0 + tx];
    __syncthreads();
    #pragma unroll
    for (int j = ty; j < 32; j += 8) {
        float x = t[tx][j];
        __nv_bfloat16 h = __float2bfloat16(x);
        long o = (long)(n0 + j) * K + k0 + tx;
        ohi[o] = h;
        olo[o] = __float2bfloat16(x - __bfloat162float(h));
    }
}

// ============================================================================
// HMMA GEMM: CTA 128x128x32, 8 warps, warp 32x64, cp.async double buffer,
// 3-term bf16 split (burst-ordered), 2 CTAs/SM.
// Epilogue: fp32 (+bias+resid) OR bf16 hi/lo split out (Chi/Clo != null).
// ============================================================================
#define LDS_ROW 80
#define ABUF    10240
#define OFF_AHI 0
#define OFF_ALO 20480
#define OFF_BHI 40960
#define OFF_BLO 61440
#define SMEM_TOT 81920

struct GemmArgs {
    const __nv_bfloat16 *Ahi, *Alo, *Bhi, *Blo;
    float* C;
    __nv_bfloat16 *Chi, *Clo;
    int Mvalid, K, ldc;
    const float *bias, *resid;
};

__device__ __forceinline__ void gemm_load_stage(
    uint32_t smb, int s, int tid, int rowBase, int colBase, int Mvalid, int K,
    const __nv_bfloat16* __restrict__ Ahi, const __nv_bfloat16* __restrict__ Alo,
    const __nv_bfloat16* __restrict__ Bhi, const __nv_bfloat16* __restrict__ Blo)
{
    const int b = s & 1;
    const long k0 = (long)s << 5;
    #pragma unroll
    for (int i = 0; i < 2; i++) {
        int idx = tid + i * 256;
        int r = idx >> 2, c = idx & 3;
        uint32_t d = smb + (uint32_t)(b * ABUF + r * LDS_ROW + c * 16);
        long go = ((long)(rowBase + r)) * K + k0 + c * 8;
        int bytes = (rowBase + r < Mvalid) ? 16 : 0;
        cp_async16(d + OFF_AHI, Ahi + go, bytes);
        cp_async16(d + OFF_ALO, Alo + go, bytes);
        long gb = ((long)(colBase + r)) * K + k0 + c * 8;
        cp_async16(d + OFF_BHI, Bhi + gb, 16);
        cp_async16(d + OFF_BLO, Blo + gb, 16);
    }
    CP_COMMIT();
}

// Burst-ordered stage compute shared by both GEMM kernels.
__device__ __forceinline__ void gemm_stage_compute(
    uint32_t aHi, uint32_t aLo, uint32_t bHi, uint32_t bLo,
    uint32_t aoffs, uint32_t boffs, float acc[2][8][4])
{
    #pragma unroll
    for (int ks = 0; ks < 2; ks++) {
        uint32_t Ah[2][4], Al[2][4];
        #pragma unroll
        for (int mi = 0; mi < 2; mi++) {
            ldsm_x4(Ah[mi], aHi + aoffs + mi * 16 * LDS_ROW + ks * 32);
            ldsm_x4(Al[mi], aLo + aoffs + mi * 16 * LDS_ROW + ks * 32);
        }
        #pragma unroll
        for (int half = 0; half < 2; half++) {
            uint32_t Bh[2][4], Bl[2][4];
            #pragma unroll
            for (int nn = 0; nn < 2; nn++) {
                const uint32_t bo = boffs + (half * 2 + nn) * 16 * LDS_ROW + ks * 32;
                ldsm_x4(Bh[nn], bHi + bo);
                ldsm_x4(Bl[nn], bLo + bo);
            }
            // burst 1: hi*hi — 8 independent accumulators
            #pragma unroll
            for (int mi = 0; mi < 2; mi++)
                #pragma unroll
                for (int j4 = 0; j4 < 4; j4++) {
                    const int ni = j4 >> 1, h = (j4 & 1) * 2;
                    mma16816(acc[mi][half * 4 + j4], Ah[mi], Bh[ni][h], Bh[ni][h + 1]);
                }
            // burst 2: hi*lo
            #pragma unroll
            for (int mi = 0; mi < 2; mi++)
                #pragma unroll
                for (int j4 = 0; j4 < 4; j4++) {
                    const int ni = j4 >> 1, h = (j4 & 1) * 2;
                    mma16816(acc[mi][half * 4 + j4], Ah[mi], Bl[ni][h], Bl[ni][h + 1]);
                }
            // burst 3: lo*hi
            #pragma unroll
            for (int mi = 0; mi < 2; mi++)
                #pragma unroll
                for (int j4 = 0; j4 < 4; j4++) {
                    const int ni = j4 >> 1, h = (j4 & 1) * 2;
                    mma16816(acc[mi][half * 4 + j4], Al[mi], Bh[ni][h], Bh[ni][h + 1]);
                }
        }
    }
}

__global__ __launch_bounds__(256, 2)
void hmma_gemm(GemmArgs args)
{
    extern __shared__ __align__(16) char smx[];
    const uint32_t smb = smem_to_u32(smx);
    const int tid = threadIdx.x;

    const __nv_bfloat16* Ahi = args.Ahi;
    const __nv_bfloat16* Alo = args.Alo;
    const __nv_bfloat16* Bhi = args.Bhi;
    const __nv_bfloat16* Blo = args.Blo;
    const int Mvalid = args.Mvalid;
    const int K = args.K, ldc = args.ldc;

    const int rowBase = blockIdx.y * 128;
    const int colBase = blockIdx.x * 128;
    const int NS = K >> 5;

    const int warp = tid >> 5, lane = tid & 31;
    const int wm = warp >> 1, wn = warp & 1;
    const int m0 = wm * 32, n0 = wn * 64;

    const uint32_t aoffs = (uint32_t)((m0 + (lane & 15)) * LDS_ROW + (lane >> 4) * 16);
    const uint32_t boffs = (uint32_t)((n0 + ((lane >> 4) & 1) * 8 + (lane & 7)) * LDS_ROW
                                      + ((lane >> 3) & 1) * 16);

    float acc[2][8][4];
    #pragma unroll
    for (int mi = 0; mi < 2; mi++)
        #pragma unroll
        for (int nj = 0; nj < 8; nj++)
            #pragma unroll
            for (int t = 0; t < 4; t++) acc[mi][nj][t] = 0.f;

    gemm_load_stage(smb, 0, tid, rowBase, colBase, Mvalid, K, Ahi, Alo, Bhi, Blo);

    for (int s = 0; s < NS; ++s) {
        if (s + 1 < NS) {
            gemm_load_stage(smb, s + 1, tid, rowBase, colBase, Mvalid, K, Ahi, Alo, Bhi, Blo);
            CP_WAIT(1);
        } else {
            CP_WAIT(0);
        }
        __syncthreads();

        const int b = s & 1;
        gemm_stage_compute(smb + OFF_AHI + b * ABUF, smb + OFF_ALO + b * ABUF,
                           smb + OFF_BHI + b * ABUF, smb + OFF_BLO + b * ABUF,
                           aoffs, boffs, acc);
        if (s + 1 < NS) __syncthreads();
    }

    // Epilogue
    const int g = lane >> 2, tig = lane & 3;
    const float* bias = args.bias;
    const float* resid = args.resid;
    #pragma unroll
    for (int mi = 0; mi < 2; mi++) {
        #pragma unroll
        for (int nj = 0; nj < 8; nj++) {
            const int r0 = rowBase + m0 + mi * 16 + g;
            const int col = colBase + n0 + nj * 8 + tig * 2;
            float2 v0 = make_float2(acc[mi][nj][0], acc[mi][nj][1]);
            float2 v1 = make_float2(acc[mi][nj][2], acc[mi][nj][3]);
            if (args.Chi) {
                if (r0 < Mvalid) {
                    long o = (long)r0 * ldc + col;
                    __nv_bfloat16 h0 = __float2bfloat16(v0.x);
                    __nv_bfloat16 h1 = __float2bfloat16(v0.y);
                    __nv_bfloat162 hh; hh.x = h0; hh.y = h1;
                    *(uint32_t*)(args.Chi + o) = *reinterpret_cast<uint32_t*>(&hh);
                    *(uint32_t*)(args.Clo + o) = pack_bf16x2(
                        v0.x - __bfloat162float(h0), v0.y - __bfloat162float(h1));
                }
                if (r0 + 8 < Mvalid) {
                    long o = (long)(r0 + 8) * ldc + col;
                    __nv_bfloat16 h0 = __float2bfloat16(v1.x);
                    __nv_bfloat16 h1 = __float2bfloat16(v1.y);
                    __nv_bfloat162 hh; hh.x = h0; hh.y = h1;
                    *(uint32_t*)(args.Chi + o) = *reinterpret_cast<uint32_t*>(&hh);
                    *(uint32_t*)(args.Clo + o) = pack_bf16x2(
                        v1.x - __bfloat162float(h0), v1.y - __bfloat162float(h1));
                }
            } else {
                float* C = args.C;
                if (bias) {
                    const float2 bi = *(const float2*)(bias + col);
                    v0.x += bi.x; v0.y += bi.y;
                    v1.x += bi.x; v1.y += bi.y;
                    if (r0 < Mvalid) {
                        const float2 rr = *(const float2*)(resid + (long)r0 * ldc + col);
                        v0.x += rr.x; v0.y += rr.y;
                    }
                    if (r0 + 8 < Mvalid) {
                        const float2 rr = *(const float2*)(resid + (long)(r0 + 8) * ldc + col);
                        v1.x += rr.x; v1.y += rr.y;
                    }
                }
                if (r0 < Mvalid)     *(float2*)(C + (long)r0 * ldc + col)       = v0;
                if (r0 + 8 < Mvalid) *(float2*)(C + (long)(r0 + 8) * ldc + col) = v1;
            }
        }
    }
}

// ============================================================================
// Packed split-K kv projection GEMM (burst-ordered compute).
// 8 M-tiles: parts 0-2 = text K (308 packed rows), 3-5 = text V,
//            6 = ipK (16 packed rows), 7 = ipV.
// grid (10, 8, 8): x = N-tile, y = part, z = K-split (256 K each, 8 stages).
// ============================================================================
__device__ __forceinline__ bool kv_map(int part, int r, long& aRow, long& cRow)
{
    aRow = 0; cRow = 0;
    if (part < 6) {
        int R = (part % 3) * 128 + r;
        if (R >= 4 * TXT) return false;
        int batch = R / TXT, rr = R - batch * TXT;
        aRow = (long)batch * ENC + rr;
        cRow = (long)(((part < 3 ? 0 : 1) * 4 + batch) * TXT + rr);
        return true;
    } else {
        if (r >= 16) return false;
        int batch = r >> 2, rr = r & 3;
        aRow = (long)batch * ENC + TXT + rr;
        cRow = (long)(((part == 6 ? 2 : 3) * 4 + batch) * TXT + rr);
        return true;
    }
}

__device__ __forceinline__ void kv_load_stage(
    uint32_t smb, int s, int tid, int part, int colBase, int kBase,
    const __nv_bfloat16* __restrict__ ehi, const __nv_bfloat16* __restrict__ elo,
    const __nv_bfloat16* __restrict__ Bhi, const __nv_bfloat16* __restrict__ Blo)
{
    const int b = s & 1;
    const int k0 = kBase + (s << 5);
    #pragma unroll
    for (int i = 0; i < 2; i++) {
        int idx = tid + i * 256;
        int r = idx >> 2, c = idx & 3;
        long aRow, cRow;
        bool valid = kv_map(part, r, aRow, cRow);
        uint32_t d = smb + (uint32_t)(b * ABUF + r * LDS_ROW + c * 16);
        long go = aRow * CROSS + k0 + c * 8;
        int bytes = valid ? 16 : 0;
        cp_async16(d + OFF_AHI, ehi + go, bytes);
        cp_async16(d + OFF_ALO, elo + go, bytes);
        long gb = (long)(colBase + r) * CROSS + k0 + c * 8;
        cp_async16(d + OFF_BHI, Bhi + gb, 16);
        cp_async16(d + OFF_BLO, Blo + gb, 16);
    }
    CP_COMMIT();
}

__global__ __launch_bounds__(256, 2)
void hmma_gemm_kv(const __nv_bfloat16* __restrict__ ehi,
                  const __nv_bfloat16* __restrict__ elo,
                  const __nv_bfloat16* __restrict__ wth,
                  const __nv_bfloat16* __restrict__ wtl,
                  float* __restrict__ pbuf)
{
    extern __shared__ __align__(16) char smx[];
    const uint32_t smb = smem_to_u32(smx);
    const int tid = threadIdx.x;
    const int part = blockIdx.y;
    const int split = blockIdx.z;
    const int colBase = blockIdx.x * 128;
    const int gemm = part < 3 ? 0 : (part < 6 ? 1 : (part == 6 ? 2 : 3));
    const __nv_bfloat16* Bhi = wth + (long)gemm * HIDDEN * CROSS;
    const __nv_bfloat16* Blo = wtl + (long)gemm * HIDDEN * CROSS;
    const int kBase = split * 256;
    float* pout = pbuf + (long)split * PART_STRIDE;

    const int warp = tid >> 5, lane = tid & 31;
    const int wm = warp >> 1, wn = warp & 1;
    const int m0 = wm * 32, n0 = wn * 64;

    const uint32_t aoffs = (uint32_t)((m0 + (lane & 15)) * LDS_ROW + (lane >> 4) * 16);
    const uint32_t boffs = (uint32_t)((n0 + ((lane >> 4) & 1) * 8 + (lane & 7)) * LDS_ROW
                                      + ((lane >> 3) & 1) * 16);

    float acc[2][8][4];
    #pragma unroll
    for (int mi = 0; mi < 2; mi++)
        #pragma unroll
        for (int nj = 0; nj < 8; nj++)
            #pragma unroll
            for (int t = 0; t < 4; t++) acc[mi][nj][t] = 0.f;

    kv_load_stage(smb, 0, tid, part, colBase, kBase, ehi, elo, Bhi, Blo);

    const int NS = 8;   // 256 K per split
    for (int s = 0; s < NS; ++s) {
        if (s + 1 < NS) {
            kv_load_stage(smb, s + 1, tid, part, colBase, kBase, ehi, elo, Bhi, Blo);
            CP_WAIT(1);
        } else {
            CP_WAIT(0);
        }
        __syncthreads();

        const int b = s & 1;
        gemm_stage_compute(smb + OFF_AHI + b * ABUF, smb + OFF_ALO + b * ABUF,
                           smb + OFF_BHI + b * ABUF, smb + OFF_BLO + b * ABUF,
                           aoffs, boffs, acc);
        if (s + 1 < NS) __syncthreads();
    }

    // Epilogue: scatter fp32 partials by packed-row map
    const int g = lane >> 2, tig = lane & 3;
    #pragma unroll
    for (int mi = 0; mi < 2; mi++) {
        #pragma unroll
        for (int nj = 0; nj < 8; nj++) {
            const int r0 = m0 + mi * 16 + g;
            const int col = colBase + n0 + nj * 8 + tig * 2;
            long aR, cR;
            if (kv_map(part, r0, aR, cR))
                *(float2*)(pout + cR * HIDDEN + col) =
                    make_float2(acc[mi][nj][0], acc[mi][nj][1]);
            if (kv_map(part, r0 + 8, aR, cR))
                *(float2*)(pout + cR * HIDDEN + col) =
                    make_float2(acc[mi][nj][2], acc[mi][nj][3]);
        }
    }
}

// Sum 8 split-K partials + bf16 hi/lo split.
__global__ __launch_bounds__(256)
void reduce_split_kv(const float* __restrict__ part,
                     __nv_bfloat16* __restrict__ hi, __nv_bfloat16* __restrict__ lo)
{
    const long n4 = PART_STRIDE / 4;
    long i = (long)blockIdx.x * 256 + threadIdx.x;
    if (i >= n4) return;
    const float4* p4 = (const float4*)part;
    float4 s = p4[i];
    #pragma unroll
    for (int k = 1; k < 8; k++) {
        float4 t = p4[i + (long)k * n4];
        s.x += t.x; s.y += t.y; s.z += t.z; s.w += t.w;
    }
    __nv_bfloat16 h0 = __float2bfloat16(s.x);
    __nv_bfloat16 h1 = __float2bfloat16(s.y);
    __nv_bfloat16 h2 = __float2bfloat16(s.z);
    __nv_bfloat16 h3 = __float2bfloat16(s.w);
    __nv_bfloat162 hA; hA.x = h0; hA.y = h1;
    __nv_bfloat162 hB; hB.x = h2; hB.y = h3;
    ((uint2*)hi)[i] = make_uint2(*reinterpret_cast<uint32_t*>(&hA),
                                 *reinterpret_cast<uint32_t*>(&hB));
    uint32_t l01 = pack_bf16x2(s.x - __bfloat162float(h0), s.y - __bfloat162float(h1));
    uint32_t l23 = pack_bf16x2(s.z - __bfloat162float(h2), s.w - __bfloat162float(h3));
    ((uint2*)lo)[i] = make_uint2(l01, l23);
}

// ============================================================================
// HMMA flash attention: CTA = 128 q-rows x 96 keys (77 text + pad + 4 ip @80).
// 8 warps, warp = 16 rows. 3-term bf16 split. V [key][dim] + ldsm.trans.
// Writes hs as bf16 hi/lo split.
// ============================================================================
#define AROW 144
#define KROW 144
#define OFF_QHI 0
#define OFF_QLO (128 * AROW)                // 18432
#define OFF_KHI (2 * 128 * AROW)            // 36864
#define OFF_KLO (OFF_KHI + 96 * KROW)       // 50688
#define OFF_VHI (OFF_KLO + 96 * KROW)       // 64512
#define OFF_VLO (OFF_VHI + 96 * KROW)       // 78336
#define SMEM_ATTN (OFF_VLO + 96 * KROW)     // 92160

__global__ __launch_bounds__(256)
void attn_mma(const __nv_bfloat16* __restrict__ qhi,
              const __nv_bfloat16* __restrict__ qlo,
              const __nv_bfloat16* __restrict__ kvhi,
              const __nv_bfloat16* __restrict__ kvlo,
              __nv_bfloat16* __restrict__ ohi, __nv_bfloat16* __restrict__ olo)
{
    extern __shared__ __align__(16) char smx[];
    const uint32_t smb = smem_to_u32(smx);
    const int tid = threadIdx.x;
    const int b = blockIdx.z, h = blockIdx.y;
    const int rowBase = blockIdx.x * 128;
    const long SLAB = (long)NB * TXT * HIDDEN;   // per-gemm stride in kv

    // Q tile: 128 rows x 64 dims (hi+lo)
    #pragma unroll
    for (int i = 0; i < 4; i++) {
        int idx = tid + i * 256;
        int r = idx >> 3, c = idx & 7;
        long src = ((long)b * SQ + rowBase + r) * HIDDEN + h * 64 + c * 8;
        uint32_t d = smb + (uint32_t)(r * AROW + c * 16);
        cp_async16(d + OFF_QHI, qhi + src, 16);
        cp_async16(d + OFF_QLO, qlo + src, 16);
    }
    // K tile: 96 rows (0-76 text K, 80-83 ipK, rest zero)
    #pragma unroll
    for (int i = 0; i < 3; i++) {
        int idx = tid + i * 256;
        int r = idx >> 3, c = idx & 7;
        int bytes = 0;
        long src = 0;
        if (r < TXT) {
            bytes = 16;
            src = (long)b * TXT * HIDDEN + (long)r * HIDDEN + h * 64 + c * 8;
        } else if (r >= 80 && r < 80 + NTOK) {
            bytes = 16;
            src = 2 * SLAB + (long)b * TXT * HIDDEN + (long)(r - 80) * HIDDEN + h * 64 + c * 8;
        }
        uint32_t d = smb + OFF_KHI + (uint32_t)(r * KROW + c * 16);
        cp_async16(d, kvhi + src, bytes);
        cp_async16(d + (OFF_KLO - OFF_KHI), kvlo + src, bytes);
    }
    // V tile: 96 rows (0-76 text V, 80-83 ipV, rest zero), [key][dim]
    #pragma unroll
    for (int i = 0; i < 3; i++) {
        int idx = tid + i * 256;
        int r = idx >> 3, c = idx & 7;
        int bytes = 0;
        long src = 0;
        if (r < TXT) {
            bytes = 16;
            src = SLAB + (long)b * TXT * HIDDEN + (long)r * HIDDEN + h * 64 + c * 8;
        } else if (r >= 80 && r < 80 + NTOK) {
            bytes = 16;
            src = 3 * SLAB + (long)b * TXT * HIDDEN + (long)(r - 80) * HIDDEN + h * 64 + c * 8;
        }
        uint32_t d = smb + OFF_VHI + (uint32_t)(r * KROW + c * 16);
        cp_async16(d, kvhi + src, bytes);
        cp_async16(d + (OFF_VLO - OFF_VHI), kvlo + src, bytes);
    }
    CP_COMMIT();
    CP_WAIT(0);
    __syncthreads();

    const int warp = tid >> 5, lane = tid & 31;
    const int m0 = warp * 16;
    const int tig = lane & 3;
    const uint32_t aoffs = smb + (uint32_t)((m0 + (lane & 15)) * AROW + (lane >> 4) * 16);
    const uint32_t kbase = smb + OFF_KHI
        + (uint32_t)((((lane >> 4) & 1) * 8 + (lane & 7)) * KROW + ((lane >> 3) & 1) * 16);

    // S = Q K^T (12 n-tiles of 8 keys = 96)
    float s[12][4];
    #pragma unroll
    for (int j = 0; j < 12; j++)
        #pragma unroll
        for (int e = 0; e < 4; e++) s[j][e] = 0.f;

    #pragma unroll
    for (int ks = 0; ks < 4; ks++) {
        uint32_t Qh[4], Ql[4];
        ldsm_x4(Qh, aoffs + ks * 32);
        ldsm_x4(Ql, aoffs + OFF_QLO + ks * 32);
        #pragma unroll
        for (int t = 0; t < 6; t++) {
            uint32_t Bh[4], Bl[4];
            ldsm_x4(Bh, kbase + t * 16 * KROW + ks * 32);
            ldsm_x4(Bl, kbase + (OFF_KLO - OFF_KHI) + t * 16 * KROW + ks * 32);
            #pragma unroll
            for (int half = 0; half < 2; half++) {
                const int j = 2 * t + half, hh = half * 2;
                mma16816(s[j], Qh, Bh[hh], Bh[hh + 1]);
                mma16816(s[j], Qh, Bl[hh], Bl[hh + 1]);
                mma16816(s[j], Ql, Bh[hh], Bh[hh + 1]);
            }
        }
    }

    // scale + mask
    const bool ipOn = (b & 1);
    float mx[2]  = {-1e30f, -1e30f};
    float mx2[2] = {-1e30f, -1e30f};
    #pragma unroll
    for (int j = 0; j < 10; j++)
        #pragma unroll
        for (int e = 0; e < 4; e++) {
            int col = j * 8 + tig * 2 + (e & 1);
            float v = s[j][e] * 0.125f;
            s[j][e] = (col < TXT) ? v : -1e30f;
            mx[e >> 1] = fmaxf(mx[e >> 1], s[j][e]);
        }
    #pragma unroll
    for (int j = 10; j < 12; j++)
        #pragma unroll
        for (int e = 0; e < 4; e++) {
            int col = j * 8 + tig * 2 + (e & 1);
            float v = s[j][e] * 0.125f;
            s[j][e] = (col >= 80 && col < 80 + NTOK) ? v : -1e30f;
            mx2[e >> 1] = fmaxf(mx2[e >> 1], s[j][e]);
        }
    #pragma unroll
    for (int off = 1; off <= 2; off <<= 1) {
        mx[0]  = fmaxf(mx[0],  __shfl_xor_sync(0xffffffffu, mx[0],  off));
        mx[1]  = fmaxf(mx[1],  __shfl_xor_sync(0xffffffffu, mx[1],  off));
        mx2[0] = fmaxf(mx2[0], __shfl_xor_sync(0xffffffffu, mx2[0], off));
        mx2[1] = fmaxf(mx2[1], __shfl_xor_sync(0xffffffffu, mx2[1], off));
    }
    float l[2] = {0.f, 0.f}, l2[2] = {0.f, 0.f};
    #pragma unroll
    for (int j = 0; j < 10; j++)
        #pragma unroll
        for (int e = 0; e < 4; e++) {
            float p = __expf(s[j][e] - mx[e >> 1]);
            s[j][e] = p;
            l[e >> 1] += p;
        }
    #pragma unroll
    for (int j = 10; j < 12; j++)
        #pragma unroll
        for (int e = 0; e < 4; e++) {
            float p = __expf(s[j][e] - mx2[e >> 1]);
            s[j][e] = p;
            l2[e >> 1] += p;
        }
    #pragma unroll
    for (int off = 1; off <= 2; off <<= 1) {
        l[0]  += __shfl_xor_sync(0xffffffffu, l[0],  off);
        l[1]  += __shfl_xor_sync(0xffffffffu, l[1],  off);
        l2[0] += __shfl_xor_sync(0xffffffffu, l2[0], off);
        l2[1] += __shfl_xor_sync(0xffffffffu, l2[1], off);
    }
    float inv[2], inv2[2];
    inv[0] = 1.f / l[0];
    inv[1] = 1.f / l[1];
    inv2[0] = ipOn ? 1.f / l2[0] : 0.f;
    inv2[1] = ipOn ? 1.f / l2[1] : 0.f;
    #pragma unroll
    for (int j = 0; j < 10; j++)
        #pragma unroll
        for (int e = 0; e < 4; e++) s[j][e] *= inv[e >> 1];
    #pragma unroll
    for (int j = 10; j < 12; j++)
        #pragma unroll
        for (int e = 0; e < 4; e++) s[j][e] *= inv2[e >> 1];

    // PV via ldsm.trans on V[key][dim]
    const uint32_t vtbase = smb + OFF_VHI
        + (uint32_t)((((lane >> 3) & 1) * 8 + (lane & 7)) * KROW + ((lane >> 4) & 1) * 16);
    float out[8][4];
    #pragma unroll
    for (int d = 0; d < 8; d++)
        #pragma unroll
        for (int e = 0; e < 4; e++) out[d][e] = 0.f;

    #pragma unroll
    for (int kk = 0; kk < 6; kk++) {
        uint32_t ah[4], al[4];
        #pragma unroll
        for (int r = 0; r < 4; r++) {
            const int t = 2 * kk + (r >> 1);
            const int pi = (r & 1) * 2;
            float v0 = s[t][pi], v1 = s[t][pi + 1];
            __nv_bfloat16 h0 = __float2bfloat16(v0);
            __nv_bfloat16 h1 = __float2bfloat16(v1);
            __nv_bfloat162 hh; hh.x = h0; hh.y = h1;
            ah[r] = *reinterpret_cast<uint32_t*>(&hh);
            al[r] = pack_bf16x2(v0 - __bfloat162float(h0), v1 - __bfloat162float(h1));
        }
        #pragma unroll
        for (int d = 0; d < 4; d++) {
            uint32_t Vh[4], Vl[4];
            ldsm_x4_t(Vh, vtbase + kk * 16 * KROW + d * 32);
            ldsm_x4_t(Vl, vtbase + (OFF_VLO - OFF_VHI) + kk * 16 * KROW + d * 32);
            #pragma unroll
            for (int half = 0; half < 2; half++) {
                const int j = 2 * d + half, hh = half * 2;
                mma16816(out[j], ah, Vh[hh], Vh[hh + 1]);
                mma16816(out[j], ah, Vl[hh], Vl[hh + 1]);
                mma16816(out[j], al, Vh[hh], Vh[hh + 1]);
            }
        }
    }

    // write hs bf16 hi/lo split
    const int g = lane >> 2;
    const long row0 = (long)b * SQ + rowBase + m0 + g;
    #pragma unroll
    for (int d = 0; d < 8; d++) {
        const int col = h * 64 + d * 8 + tig * 2;
        #pragma unroll
        for (int rr = 0; rr < 2; rr++) {
            float v0 = out[d][rr * 2 + 0], v1 = out[d][rr * 2 + 1];
            long o = (row0 + rr * 8) * HIDDEN + col;
            __nv_bfloat16 h0 = __float2bfloat16(v0);
            __nv_bfloat16 h1 = __float2bfloat16(v1);
            __nv_bfloat162 hh; hh.x = h0; hh.y = h1;
            *(uint32_t*)(ohi + o) = *reinterpret_cast<uint32_t*>(&hh);
            *(uint32_t*)(olo + o) = pack_bf16x2(
                v0 - __bfloat162float(h0), v1 - __bfloat162float(h1));
        }
    }
}

// ============================================================================
// Launcher
// ============================================================================
extern "C" void kernel_launch(void* const* d_in, const int* in_sizes, int n_in,
                              void* d_out, int out_size)
{
    const float* hidden = (const float*)d_in[0];
    const float* enc    = (const float*)d_in[1];
    const float* Wq     = (const float*)d_in[2];
    const float* Wk     = (const float*)d_in[3];
    const float* Wv     = (const float*)d_in[4];
    const float* Wk_ip  = (const float*)d_in[5];
    const float* Wv_ip  = (const float*)d_in[6];
    const float* Wout   = (const float*)d_in[7];
    const float* b_out  = (const float*)d_in[8];
    float* out = (float*)d_out;

    static bool attr_set = false;
    if (!attr_set) {
        cudaFuncSetAttribute(hmma_gemm, cudaFuncAttributeMaxDynamicSharedMemorySize, SMEM_TOT);
        cudaFuncSetAttribute(hmma_gemm_kv, cudaFuncAttributeMaxDynamicSharedMemorySize, SMEM_TOT);
        cudaFuncSetAttribute(attn_mma, cudaFuncAttributeMaxDynamicSharedMemorySize, SMEM_ATTN);
        attr_set = true;
    }

    __nv_bfloat16 *ahi, *alo, *qhi, *qlo, *ehi, *elo;
    __nv_bfloat16 *wqh, *wql, *wth, *wtl, *woh, *wol, *kvh, *kvl;
    float* pbuf;
    cudaGetSymbolAddress((void**)&ahi, g_ahi);
    cudaGetSymbolAddress((void**)&alo, g_alo);
    cudaGetSymbolAddress((void**)&qhi, g_qhi);
    cudaGetSymbolAddress((void**)&qlo, g_qlo);
    cudaGetSymbolAddress((void**)&ehi, g_ehi);
    cudaGetSymbolAddress((void**)&elo, g_elo);
    cudaGetSymbolAddress((void**)&wqh, g_wqT_hi);
    cudaGetSymbolAddress((void**)&wql, g_wqT_lo);
    cudaGetSymbolAddress((void**)&wth, g_wT_hi);
    cudaGetSymbolAddress((void**)&wtl, g_wT_lo);
    cudaGetSymbolAddress((void**)&woh, g_woutT_hi);
    cudaGetSymbolAddress((void**)&wol, g_woutT_lo);
    cudaGetSymbolAddress((void**)&kvh, g_kvhi);
    cudaGetSymbolAddress((void**)&kvl, g_kvlo);
    cudaGetSymbolAddress((void**)&pbuf, g_part);

    const int M_big = NB * SQ;  // 16384
    const long WSLAB = (long)HIDDEN * CROSS;

    // 1) activation splits
    {
        int n4 = M_big * HIDDEN / 4;
        split_kernel<<<(n4 + 255) / 256, 256>>>(hidden, ahi, alo, n4);
    }
    {
        int n4 = NB * ENC * CROSS / 4;
        split_kernel<<<(n4 + 255) / 256, 256>>>(enc, ehi, elo, n4);
    }

    // 2) all weight transposes+splits in one launch
    {
        TSArgs t;
        t.src[0] = Wq;    t.dhi[0] = wqh;             t.dlo[0] = wql;             t.K[0] = HIDDEN;
        t.src[1] = Wk;    t.dhi[1] = wth + 0 * WSLAB; t.dlo[1] = wtl + 0 * WSLAB; t.K[1] = CROSS;
        t.src[2] = Wv;    t.dhi[2] = wth + 1 * WSLAB; t.dlo[2] = wtl + 1 * WSLAB; t.K[2] = CROSS;
        t.src[3] = Wk_ip; t.dhi[3] = wth + 2 * WSLAB; t.dlo[3] = wtl + 2 * WSLAB; t.K[3] = CROSS;
        t.src[4] = Wv_ip; t.dhi[4] = wth + 3 * WSLAB; t.dlo[4] = wtl + 3 * WSLAB; t.K[4] = CROSS;
        t.src[5] = Wout;  t.dhi[5] = woh;             t.dlo[5] = wol;             t.K[5] = HIDDEN;
        transpose_split_all<<<dim3(HIDDEN / 32, CROSS / 32, 6), dim3(32, 8)>>>(t);
    }

    // 3) Q = hidden @ Wq  -> bf16 hi/lo split
    {
        GemmArgs a = {ahi, alo, wqh, wql, nullptr, qhi, qlo,
                      M_big, HIDDEN, HIDDEN, nullptr, nullptr};
        hmma_gemm<<<dim3(HIDDEN / 128, M_big / 128, 1), 256, SMEM_TOT>>>(a);
    }

    // 4) packed split-K K/V/ipK/ipV projections -> fp32 partials -> reduce+split
    hmma_gemm_kv<<<dim3(HIDDEN / 128, 8, 8), 256, SMEM_TOT>>>(ehi, elo, wth, wtl, pbuf);
    {
        long n4 = PART_STRIDE / 4;
        reduce_split_kv<<<(int)((n4 + 255) / 256), 256>>>(pbuf, kvh, kvl);
    }

    // 5) HMMA attention -> hs bf16 hi/lo (reuses ahi/alo)
    attn_mma<<<dim3(SQ / 128, NHEADS, NB), 256, SMEM_ATTN>>>(qhi, qlo, kvh, kvl, ahi, alo);

    // 6) out = hs @ Wout + b_out + residual (fp32)
    {
        GemmArgs a = {ahi, alo, woh, wol, out, nullptr, nullptr,
                      M_big, HIDDEN, HIDDEN, b_out, hidden};
        hmma_gemm<<<dim3(HIDDEN / 128, M_big / 128, 1), 256, SMEM_TOT>>>(a);
    }
}

// round 9
// speedup vs baseline: 1.0798x; 1.0798x over previous
#include <cuda_runtime.h>
#include <cuda_bf16.h>
#include <cstdint>

#define NHEADS 20
#define HEAD_DIM 64
#define HIDDEN 1280
#define CROSS 2048
#define NB 4
#define SQ 4096
#define TXT 77
#define NTOK 4
#define ENC (TXT + NTOK)

// ============================================================================
// PTX helpers (baseline-family only: mma.sync / ldmatrix / cp.async)
// ============================================================================
__device__ __forceinline__ uint32_t smem_to_u32(const void* smem_ptr) {
    uint32_t addr;
    asm("{ .reg .u64 tmp; cvta.to.shared.u64 tmp, %1; cvt.u32.u64 %0, tmp; }"
        : "=r"(addr) : "l"(smem_ptr));
    return addr;
}

__device__ __forceinline__ void cp_async16(uint32_t dst, const void* src, int bytes) {
    asm volatile("cp.async.cg.shared.global [%0], [%1], 16, %2;"
                 :: "r"(dst), "l"(src), "r"(bytes));
}
#define CP_COMMIT() asm volatile("cp.async.commit_group;" ::: "memory")
#define CP_WAIT(N)  asm volatile("cp.async.wait_group %0;" :: "n"(N) : "memory")

__device__ __forceinline__ void ldsm_x4(uint32_t* r, uint32_t a) {
    asm volatile("ldmatrix.sync.aligned.m8n8.x4.shared.b16 {%0,%1,%2,%3}, [%4];"
                 : "=r"(r[0]), "=r"(r[1]), "=r"(r[2]), "=r"(r[3]) : "r"(a));
}

__device__ __forceinline__ void ldsm_x4_t(uint32_t* r, uint32_t a) {
    asm volatile("ldmatrix.sync.aligned.m8n8.x4.trans.shared.b16 {%0,%1,%2,%3}, [%4];"
                 : "=r"(r[0]), "=r"(r[1]), "=r"(r[2]), "=r"(r[3]) : "r"(a));
}

__device__ __forceinline__ void mma16816(float* c, const uint32_t* a,
                                         uint32_t b0, uint32_t b1) {
    asm volatile(
        "mma.sync.aligned.m16n8k16.row.col.f32.bf16.bf16.f32 "
        "{%0,%1,%2,%3},{%4,%5,%6,%7},{%8,%9},{%0,%1,%2,%3};"
        : "+f"(c[0]), "+f"(c[1]), "+f"(c[2]), "+f"(c[3])
        : "r"(a[0]), "r"(a[1]), "r"(a[2]), "r"(a[3]), "r"(b0), "r"(b1));
}

__device__ __forceinline__ uint32_t pack_bf16x2(float a, float b) {
    __nv_bfloat162 t;
    t.x = __float2bfloat16(a);
    t.y = __float2bfloat16(b);
    return *reinterpret_cast<uint32_t*>(&t);
}

// ============================================================================
// Scratch (static device allocations)
// ============================================================================
#define PART_STRIDE ((long)16 * TXT * HIDDEN)   // floats per split-K partial

__device__ __nv_bfloat16 g_ahi[NB * SQ * HIDDEN];
__device__ __nv_bfloat16 g_alo[NB * SQ * HIDDEN];
__device__ __nv_bfloat16 g_qhi[NB * SQ * HIDDEN];
__device__ __nv_bfloat16 g_qlo[NB * SQ * HIDDEN];
__device__ __nv_bfloat16 g_ehi[NB * ENC * CROSS];
__device__ __nv_bfloat16 g_elo[NB * ENC * CROSS];
__device__ __nv_bfloat16 g_wqT_hi[HIDDEN * HIDDEN];
__device__ __nv_bfloat16 g_wqT_lo[HIDDEN * HIDDEN];
__device__ __nv_bfloat16 g_wT_hi[4 * HIDDEN * CROSS];
__device__ __nv_bfloat16 g_wT_lo[4 * HIDDEN * CROSS];
__device__ __nv_bfloat16 g_woutT_hi[HIDDEN * HIDDEN];
__device__ __nv_bfloat16 g_woutT_lo[HIDDEN * HIDDEN];
__device__ __nv_bfloat16 g_kvhi[4 * NB * TXT * HIDDEN];  // k,v,ipk,ipv
__device__ __nv_bfloat16 g_kvlo[4 * NB * TXT * HIDDEN];
__device__ float g_part[8 * 16 * TXT * HIDDEN];          // split-K partials

// ============================================================================
// fp32 -> bf16 hi/lo split
// ============================================================================
__global__ __launch_bounds__(256)
void split_kernel(const float* __restrict__ in, __nv_bfloat16* __restrict__ hi,
                  __nv_bfloat16* __restrict__ lo, int n4)
{
    int i = blockIdx.x * blockDim.x + threadIdx.x;
    if (i >= n4) return;
    float4 x = ((const float4*)in)[i];
    __nv_bfloat16 h0 = __float2bfloat16(x.x);
    __nv_bfloat16 h1 = __float2bfloat16(x.y);
    __nv_bfloat16 h2 = __float2bfloat16(x.z);
    __nv_bfloat16 h3 = __float2bfloat16(x.w);
    __nv_bfloat162 hA; hA.x = h0; hA.y = h1;
    __nv_bfloat162 hB; hB.x = h2; hB.y = h3;
    ((__nv_bfloat162*)hi)[2 * i]     = hA;
    ((__nv_bfloat162*)hi)[2 * i + 1] = hB;
    __nv_bfloat162 lA;
    lA.x = __float2bfloat16(x.x - __bfloat162float(h0));
    lA.y = __float2bfloat16(x.y - __bfloat162float(h1));
    __nv_bfloat162 lB;
    lB.x = __float2bfloat16(x.z - __bfloat162float(h2));
    lB.y = __float2bfloat16(x.w - __bfloat162float(h3));
    ((__nv_bfloat162*)lo)[2 * i]     = lA;
    ((__nv_bfloat162*)lo)[2 * i + 1] = lB;
}

// ============================================================================
// Merged transpose + split of all 6 weights (grid.z selects weight).
// ============================================================================
struct TSArgs {
    const float* src[6];
    __nv_bfloat16* dhi[6];
    __nv_bfloat16* dlo[6];
    int K[6];
};

__global__ __launch_bounds__(256)
void transpose_split_all(TSArgs args)
{
    const int w = blockIdx.z;
    const int K = args.K[w];
    const int k0 = blockIdx.y * 32;
    if (k0 >= K) return;
    const float* in = args.src[w];
    __nv_bfloat16* ohi = args.dhi[w];
    __nv_bfloat16* olo = args.dlo[w];

    __shared__ float t[32][33];
    const int tx = threadIdx.x, ty = threadIdx.y;
    const int n0 = blockIdx.x * 32;
    #pragma unroll
    for (int j = ty; j < 32; j += 8)
        t[j][tx] = in[(long)(k0 + j) * HIDDEN + n0 + tx];
    __syncthreads();
    #pragma unroll
    for (int j = ty; j < 32; j += 8) {
        float x = t[tx][j];
        __nv_bfloat16 h = __float2bfloat16(x);
        long o = (long)(n0 + j) * K + k0 + tx;
        ohi[o] = h;
        olo[o] = __float2bfloat16(x - __bfloat162float(h));
    }
}

// ============================================================================
// Shared GEMM pieces: CTA 128x128x32, 8 warps, warp 32x64, cp.async double
// buffer, 3-term bf16 split (round-7 interleaved MMA order).
// ============================================================================
#define LDS_ROW 80
#define ABUF    10240
#define OFF_AHI 0
#define OFF_ALO 20480
#define OFF_BHI 40960
#define OFF_BLO 61440
#define SMEM_TOT 81920

// Round-7 interleaved per-stage compute (DO NOT reorder MMAs — see R5/R8 post-mortems).
__device__ __forceinline__ void gemm_stage_compute(
    uint32_t aHi, uint32_t aLo, uint32_t bHi, uint32_t bLo,
    uint32_t aoffs, uint32_t boffs, float acc[2][8][4])
{
    #pragma unroll
    for (int ks = 0; ks < 2; ks++) {
        uint32_t Ah[2][4], Al[2][4];
        #pragma unroll
        for (int mi = 0; mi < 2; mi++) {
            ldsm_x4(Ah[mi], aHi + aoffs + mi * 16 * LDS_ROW + ks * 32);
            ldsm_x4(Al[mi], aLo + aoffs + mi * 16 * LDS_ROW + ks * 32);
        }
        #pragma unroll
        for (int half = 0; half < 2; half++) {
            uint32_t Bh[2][4], Bl[2][4];
            #pragma unroll
            for (int nn = 0; nn < 2; nn++) {
                const uint32_t bo = boffs + (half * 2 + nn) * 16 * LDS_ROW + ks * 32;
                ldsm_x4(Bh[nn], bHi + bo);
                ldsm_x4(Bl[nn], bLo + bo);
            }
            #pragma unroll
            for (int mi = 0; mi < 2; mi++) {
                #pragma unroll
                for (int j4 = 0; j4 < 4; j4++) {
                    const int ni = j4 >> 1, h = (j4 & 1) * 2;
                    float* a = acc[mi][half * 4 + j4];
                    mma16816(a, Ah[mi], Bh[ni][h], Bh[ni][h + 1]);
                    mma16816(a, Ah[mi], Bl[ni][h], Bl[ni][h + 1]);
                    mma16816(a, Al[mi], Bh[ni][h], Bh[ni][h + 1]);
                }
            }
        }
    }
}

// kv packed-row map: parts 0-2 text K (4x77 rows), 3-5 text V, 6 ipK (16), 7 ipV.
__device__ __forceinline__ bool kv_map(int part, int r, long& aRow, long& cRow)
{
    aRow = 0; cRow = 0;
    if (part < 6) {
        int R = (part % 3) * 128 + r;
        if (R >= 4 * TXT) return false;
        int batch = R / TXT, rr = R - batch * TXT;
        aRow = (long)batch * ENC + rr;
        cRow = (long)(((part < 3 ? 0 : 1) * 4 + batch) * TXT + rr);
        return true;
    } else {
        if (r >= 16) return false;
        int batch = r >> 2, rr = r & 3;
        aRow = (long)batch * ENC + TXT + rr;
        cRow = (long)(((part == 6 ? 2 : 3) * 4 + batch) * TXT + rr);
        return true;
    }
}

// ============================================================================
// Merged Q-projection + packed split-K kv-projection GEMM.
// 1-D grid of 1920 CTAs: bid < 1280 -> Q tile (40 stages),
// bid >= 1280 -> kv tile (8 stages). kv CTAs backfill the Q tail wave.
// ============================================================================
struct QKVArgs {
    const __nv_bfloat16 *ahi, *alo, *ehi, *elo;
    const __nv_bfloat16 *wqh, *wql, *wth, *wtl;
    __nv_bfloat16 *qhi, *qlo;
    float* pbuf;
};

__global__ __launch_bounds__(256, 2)
void hmma_gemm_qkv(QKVArgs args)
{
    extern __shared__ __align__(16) char smx[];
    const uint32_t smb = smem_to_u32(smx);
    const int tid = threadIdx.x;
    const int bid = blockIdx.x;
    const bool isQ = bid < 1280;

    // per-thread A-load row mapping (rows r0 = tid>>2 and r0+64, col chunk tid&3)
    const int lr0 = tid >> 2;
    const int cch = tid & 3;

    const __nv_bfloat16 *Ahi, *Alo, *Bhi, *Blo;
    int K, NS, kBase, colBase, rowBase = 0, part = 0, split = 0;
    int aRow[2];
    int aBytes[2];

    if (isQ) {
        rowBase = (bid / 10) * 128;
        colBase = (bid % 10) * 128;
        Ahi = args.ahi; Alo = args.alo;
        Bhi = args.wqh; Blo = args.wql;
        K = HIDDEN; NS = 40; kBase = 0;
        aRow[0] = rowBase + lr0;
        aRow[1] = rowBase + lr0 + 64;
        aBytes[0] = 16; aBytes[1] = 16;   // M=16384, always in range
    } else {
        const int t = bid - 1280;
        colBase = (t % 10) * 128;
        part = (t / 10) & 7;
        split = t / 80;
        const int gemm = part < 3 ? 0 : (part < 6 ? 1 : (part == 6 ? 2 : 3));
        Ahi = args.ehi; Alo = args.elo;
        Bhi = args.wth + (long)gemm * HIDDEN * CROSS;
        Blo = args.wtl + (long)gemm * HIDDEN * CROSS;
        K = CROSS; NS = 8; kBase = split * 256;
        long ar, cr;
        aBytes[0] = kv_map(part, lr0, ar, cr) ? 16 : 0;      aRow[0] = (int)ar;
        aBytes[1] = kv_map(part, lr0 + 64, ar, cr) ? 16 : 0; aRow[1] = (int)ar;
    }

    const int warp = tid >> 5, lane = tid & 31;
    const int wm = warp >> 1, wn = warp & 1;
    const int m0 = wm * 32, n0 = wn * 64;

    const uint32_t aoffs = (uint32_t)((m0 + (lane & 15)) * LDS_ROW + (lane >> 4) * 16);
    const uint32_t boffs = (uint32_t)((n0 + ((lane >> 4) & 1) * 8 + (lane & 7)) * LDS_ROW
                                      + ((lane >> 3) & 1) * 16);

    float acc[2][8][4];
    #pragma unroll
    for (int mi = 0; mi < 2; mi++)
        #pragma unroll
        for (int nj = 0; nj < 8; nj++)
            #pragma unroll
            for (int t = 0; t < 4; t++) acc[mi][nj][t] = 0.f;

    // uniform load-stage (A rows via precomputed map; B rows linear)
    auto load_stage = [&](int s) {
        const int b = s & 1;
        const int k0 = kBase + (s << 5);
        #pragma unroll
        for (int i = 0; i < 2; i++) {
            const int r = lr0 + i * 64;
            uint32_t d = smb + (uint32_t)(b * ABUF + r * LDS_ROW + cch * 16);
            long go = (long)aRow[i] * K + k0 + cch * 8;
            cp_async16(d + OFF_AHI, Ahi + go, aBytes[i]);
            cp_async16(d + OFF_ALO, Alo + go, aBytes[i]);
            long gb = (long)(colBase + r) * K + k0 + cch * 8;
            cp_async16(d + OFF_BHI, Bhi + gb, 16);
            cp_async16(d + OFF_BLO, Blo + gb, 16);
        }
        CP_COMMIT();
    };

    load_stage(0);
    for (int s = 0; s < NS; ++s) {
        if (s + 1 < NS) {
            load_stage(s + 1);
            CP_WAIT(1);
        } else {
            CP_WAIT(0);
        }
        __syncthreads();
        const int b = s & 1;
        gemm_stage_compute(smb + OFF_AHI + b * ABUF, smb + OFF_ALO + b * ABUF,
                           smb + OFF_BHI + b * ABUF, smb + OFF_BLO + b * ABUF,
                           aoffs, boffs, acc);
        __syncthreads();
    }

    // Epilogue
    const int g = lane >> 2, tig = lane & 3;
    if (isQ) {
        #pragma unroll
        for (int mi = 0; mi < 2; mi++) {
            #pragma unroll
            for (int nj = 0; nj < 8; nj++) {
                const int r0 = rowBase + m0 + mi * 16 + g;
                const int col = colBase + n0 + nj * 8 + tig * 2;
                #pragma unroll
                for (int rr = 0; rr < 2; rr++) {
                    float v0 = acc[mi][nj][rr * 2 + 0];
                    float v1 = acc[mi][nj][rr * 2 + 1];
                    long o = (long)(r0 + rr * 8) * HIDDEN + col;
                    __nv_bfloat16 h0 = __float2bfloat16(v0);
                    __nv_bfloat16 h1 = __float2bfloat16(v1);
                    __nv_bfloat162 hh; hh.x = h0; hh.y = h1;
                    *(uint32_t*)(args.qhi + o) = *reinterpret_cast<uint32_t*>(&hh);
                    *(uint32_t*)(args.qlo + o) = pack_bf16x2(
                        v0 - __bfloat162float(h0), v1 - __bfloat162float(h1));
                }
            }
        }
    } else {
        float* pout = args.pbuf + (long)split * PART_STRIDE;
        #pragma unroll
        for (int mi = 0; mi < 2; mi++) {
            #pragma unroll
            for (int nj = 0; nj < 8; nj++) {
                const int r0 = m0 + mi * 16 + g;
                const int col = colBase + n0 + nj * 8 + tig * 2;
                long aR, cR;
                if (kv_map(part, r0, aR, cR))
                    *(float2*)(pout + cR * HIDDEN + col) =
                        make_float2(acc[mi][nj][0], acc[mi][nj][1]);
                if (kv_map(part, r0 + 8, aR, cR))
                    *(float2*)(pout + cR * HIDDEN + col) =
                        make_float2(acc[mi][nj][2], acc[mi][nj][3]);
            }
        }
    }
}

// ============================================================================
// Out-projection GEMM (round-7 config, interleaved order, fused bias+resid).
// ============================================================================
struct GemmArgs {
    const __nv_bfloat16 *Ahi, *Alo, *Bhi, *Blo;
    float* C;
    int Mvalid, K, ldc;
    const float *bias, *resid;
};

__device__ __forceinline__ void gemm_load_stage(
    uint32_t smb, int s, int tid, int rowBase, int colBase, int Mvalid, int K,
    const __nv_bfloat16* __restrict__ Ahi, const __nv_bfloat16* __restrict__ Alo,
    const __nv_bfloat16* __restrict__ Bhi, const __nv_bfloat16* __restrict__ Blo)
{
    const int b = s & 1;
    const long k0 = (long)s << 5;
    #pragma unroll
    for (int i = 0; i < 2; i++) {
        int idx = tid + i * 256;
        int r = idx >> 2, c = idx & 3;
        uint32_t d = smb + (uint32_t)(b * ABUF + r * LDS_ROW + c * 16);
        long go = ((long)(rowBase + r)) * K + k0 + c * 8;
        int bytes = (rowBase + r < Mvalid) ? 16 : 0;
        cp_async16(d + OFF_AHI, Ahi + go, bytes);
        cp_async16(d + OFF_ALO, Alo + go, bytes);
        long gb = ((long)(colBase + r)) * K + k0 + c * 8;
        cp_async16(d + OFF_BHI, Bhi + gb, 16);
        cp_async16(d + OFF_BLO, Blo + gb, 16);
    }
    CP_COMMIT();
}

__global__ __launch_bounds__(256, 2)
void hmma_gemm(GemmArgs args)
{
    extern __shared__ __align__(16) char smx[];
    const uint32_t smb = smem_to_u32(smx);
    const int tid = threadIdx.x;

    const __nv_bfloat16* Ahi = args.Ahi;
    const __nv_bfloat16* Alo = args.Alo;
    const __nv_bfloat16* Bhi = args.Bhi;
    const __nv_bfloat16* Blo = args.Blo;
    const int Mvalid = args.Mvalid;
    const int K = args.K, ldc = args.ldc;

    const int rowBase = blockIdx.y * 128;
    const int colBase = blockIdx.x * 128;
    const int NS = K >> 5;

    const int warp = tid >> 5, lane = tid & 31;
    const int wm = warp >> 1, wn = warp & 1;
    const int m0 = wm * 32, n0 = wn * 64;

    const uint32_t aoffs = (uint32_t)((m0 + (lane & 15)) * LDS_ROW + (lane >> 4) * 16);
    const uint32_t boffs = (uint32_t)((n0 + ((lane >> 4) & 1) * 8 + (lane & 7)) * LDS_ROW
                                      + ((lane >> 3) & 1) * 16);

    float acc[2][8][4];
    #pragma unroll
    for (int mi = 0; mi < 2; mi++)
        #pragma unroll
        for (int nj = 0; nj < 8; nj++)
            #pragma unroll
            for (int t = 0; t < 4; t++) acc[mi][nj][t] = 0.f;

    gemm_load_stage(smb, 0, tid, rowBase, colBase, Mvalid, K, Ahi, Alo, Bhi, Blo);

    for (int s = 0; s < NS; ++s) {
        if (s + 1 < NS) {
            gemm_load_stage(smb, s + 1, tid, rowBase, colBase, Mvalid, K, Ahi, Alo, Bhi, Blo);
            CP_WAIT(1);
        } else {
            CP_WAIT(0);
        }
        __syncthreads();

        const int b = s & 1;
        gemm_stage_compute(smb + OFF_AHI + b * ABUF, smb + OFF_ALO + b * ABUF,
                           smb + OFF_BHI + b * ABUF, smb + OFF_BLO + b * ABUF,
                           aoffs, boffs, acc);
        __syncthreads();
    }

    // Epilogue: fp32 + bias + residual
    const int g = lane >> 2, tig = lane & 3;
    const float* bias = args.bias;
    const float* resid = args.resid;
    #pragma unroll
    for (int mi = 0; mi < 2; mi++) {
        #pragma unroll
        for (int nj = 0; nj < 8; nj++) {
            const int r0 = rowBase + m0 + mi * 16 + g;
            const int col = colBase + n0 + nj * 8 + tig * 2;
            float2 v0 = make_float2(acc[mi][nj][0], acc[mi][nj][1]);
            float2 v1 = make_float2(acc[mi][nj][2], acc[mi][nj][3]);
            const float2 bi = *(const float2*)(bias + col);
            v0.x += bi.x; v0.y += bi.y;
            v1.x += bi.x; v1.y += bi.y;
            const float2 rr0 = *(const float2*)(resid + (long)r0 * ldc + col);
            v0.x += rr0.x; v0.y += rr0.y;
            const float2 rr1 = *(const float2*)(resid + (long)(r0 + 8) * ldc + col);
            v1.x += rr1.x; v1.y += rr1.y;
            *(float2*)(args.C + (long)r0 * ldc + col)       = v0;
            *(float2*)(args.C + (long)(r0 + 8) * ldc + col) = v1;
        }
    }
}

// Sum 8 split-K partials + bf16 hi/lo split.
__global__ __launch_bounds__(256)
void reduce_split_kv(const float* __restrict__ part,
                     __nv_bfloat16* __restrict__ hi, __nv_bfloat16* __restrict__ lo)
{
    const long n4 = PART_STRIDE / 4;
    long i = (long)blockIdx.x * 256 + threadIdx.x;
    if (i >= n4) return;
    const float4* p4 = (const float4*)part;
    float4 s = p4[i];
    #pragma unroll
    for (int k = 1; k < 8; k++) {
        float4 t = p4[i + (long)k * n4];
        s.x += t.x; s.y += t.y; s.z += t.z; s.w += t.w;
    }
    __nv_bfloat16 h0 = __float2bfloat16(s.x);
    __nv_bfloat16 h1 = __float2bfloat16(s.y);
    __nv_bfloat16 h2 = __float2bfloat16(s.z);
    __nv_bfloat16 h3 = __float2bfloat16(s.w);
    __nv_bfloat162 hA; hA.x = h0; hA.y = h1;
    __nv_bfloat162 hB; hB.x = h2; hB.y = h3;
    ((uint2*)hi)[i] = make_uint2(*reinterpret_cast<uint32_t*>(&hA),
                                 *reinterpret_cast<uint32_t*>(&hB));
    uint32_t l01 = pack_bf16x2(s.x - __bfloat162float(h0), s.y - __bfloat162float(h1));
    uint32_t l23 = pack_bf16x2(s.z - __bfloat162float(h2), s.w - __bfloat162float(h3));
    ((uint2*)lo)[i] = make_uint2(l01, l23);
}

// ============================================================================
// HMMA flash attention: CTA = 128 q-rows x 96 keys (77 text + pad + 4 ip @80).
// 8 warps, warp = 16 rows. 3-term bf16 split. V [key][dim] + ldsm.trans.
// Writes hs as bf16 hi/lo split.
// ============================================================================
#define AROW 144
#define KROW 144
#define OFF_QHI 0
#define OFF_QLO (128 * AROW)
#define OFF_KHI (2 * 128 * AROW)
#define OFF_KLO (OFF_KHI + 96 * KROW)
#define OFF_VHI (OFF_KLO + 96 * KROW)
#define OFF_VLO (OFF_VHI + 96 * KROW)
#define SMEM_ATTN (OFF_VLO + 96 * KROW)

__global__ __launch_bounds__(256)
void attn_mma(const __nv_bfloat16* __restrict__ qhi,
              const __nv_bfloat16* __restrict__ qlo,
              const __nv_bfloat16* __restrict__ kvhi,
              const __nv_bfloat16* __restrict__ kvlo,
              __nv_bfloat16* __restrict__ ohi, __nv_bfloat16* __restrict__ olo)
{
    extern __shared__ __align__(16) char smx[];
    const uint32_t smb = smem_to_u32(smx);
    const int tid = threadIdx.x;
    const int b = blockIdx.z, h = blockIdx.y;
    const int rowBase = blockIdx.x * 128;
    const long SLAB = (long)NB * TXT * HIDDEN;

    #pragma unroll
    for (int i = 0; i < 4; i++) {
        int idx = tid + i * 256;
        int r = idx >> 3, c = idx & 7;
        long src = ((long)b * SQ + rowBase + r) * HIDDEN + h * 64 + c * 8;
        uint32_t d = smb + (uint32_t)(r * AROW + c * 16);
        cp_async16(d + OFF_QHI, qhi + src, 16);
        cp_async16(d + OFF_QLO, qlo + src, 16);
    }
    #pragma unroll
    for (int i = 0; i < 3; i++) {
        int idx = tid + i * 256;
        int r = idx >> 3, c = idx & 7;
        int bytes = 0;
        long src = 0;
        if (r < TXT) {
            bytes = 16;
            src = (long)b * TXT * HIDDEN + (long)r * HIDDEN + h * 64 + c * 8;
        } else if (r >= 80 && r < 80 + NTOK) {
            bytes = 16;
            src = 2 * SLAB + (long)b * TXT * HIDDEN + (long)(r - 80) * HIDDEN + h * 64 + c * 8;
        }
        uint32_t d = smb + OFF_KHI + (uint32_t)(r * KROW + c * 16);
        cp_async16(d, kvhi + src, bytes);
        cp_async16(d + (OFF_KLO - OFF_KHI), kvlo + src, bytes);
    }
    #pragma unroll
    for (int i = 0; i < 3; i++) {
        int idx = tid + i * 256;
        int r = idx >> 3, c = idx & 7;
        int bytes = 0;
        long src = 0;
        if (r < TXT) {
            bytes = 16;
            src = SLAB + (long)b * TXT * HIDDEN + (long)r * HIDDEN + h * 64 + c * 8;
        } else if (r >= 80 && r < 80 + NTOK) {
            bytes = 16;
            src = 3 * SLAB + (long)b * TXT * HIDDEN + (long)(r - 80) * HIDDEN + h * 64 + c * 8;
        }
        uint32_t d = smb + OFF_VHI + (uint32_t)(r * KROW + c * 16);
        cp_async16(d, kvhi + src, bytes);
        cp_async16(d + (OFF_VLO - OFF_VHI), kvlo + src, bytes);
    }
    CP_COMMIT();
    CP_WAIT(0);
    __syncthreads();

    const int warp = tid >> 5, lane = tid & 31;
    const int m0 = warp * 16;
    const int tig = lane & 3;
    const uint32_t aoffs = smb + (uint32_t)((m0 + (lane & 15)) * AROW + (lane >> 4) * 16);
    const uint32_t kbase = smb + OFF_KHI
        + (uint32_t)((((lane >> 4) & 1) * 8 + (lane & 7)) * KROW + ((lane >> 3) & 1) * 16);

    float s[12][4];
    #pragma unroll
    for (int j = 0; j < 12; j++)
        #pragma unroll
        for (int e = 0; e < 4; e++) s[j][e] = 0.f;

    #pragma unroll
    for (int ks = 0; ks < 4; ks++) {
        uint32_t Qh[4], Ql[4];
        ldsm_x4(Qh, aoffs + ks * 32);
        ldsm_x4(Ql, aoffs + OFF_QLO + ks * 32);
        #pragma unroll
        for (int t = 0; t < 6; t++) {
            uint32_t Bh[4], Bl[4];
            ldsm_x4(Bh, kbase + t * 16 * KROW + ks * 32);
            ldsm_x4(Bl, kbase + (OFF_KLO - OFF_KHI) + t * 16 * KROW + ks * 32);
            #pragma unroll
            for (int half = 0; half < 2; half++) {
                const int j = 2 * t + half, hh = half * 2;
                mma16816(s[j], Qh, Bh[hh], Bh[hh + 1]);
                mma16816(s[j], Qh, Bl[hh], Bl[hh + 1]);
                mma16816(s[j], Ql, Bh[hh], Bh[hh + 1]);
            }
        }
    }

    const bool ipOn = (b & 1);
    float mx[2]  = {-1e30f, -1e30f};
    float mx2[2] = {-1e30f, -1e30f};
    #pragma unroll
    for (int j = 0; j < 10; j++)
        #pragma unroll
        for (int e = 0; e < 4; e++) {
            int col = j * 8 + tig * 2 + (e & 1);
            float v = s[j][e] * 0.125f;
            s[j][e] = (col < TXT) ? v : -1e30f;
            mx[e >> 1] = fmaxf(mx[e >> 1], s[j][e]);
        }
    #pragma unroll
    for (int j = 10; j < 12; j++)
        #pragma unroll
        for (int e = 0; e < 4; e++) {
            int col = j * 8 + tig * 2 + (e & 1);
            float v = s[j][e] * 0.125f;
            s[j][e] = (col >= 80 && col < 80 + NTOK) ? v : -1e30f;
            mx2[e >> 1] = fmaxf(mx2[e >> 1], s[j][e]);
        }
    #pragma unroll
    for (int off = 1; off <= 2; off <<= 1) {
        mx[0]  = fmaxf(mx[0],  __shfl_xor_sync(0xffffffffu, mx[0],  off));
        mx[1]  = fmaxf(mx[1],  __shfl_xor_sync(0xffffffffu, mx[1],  off));
        mx2[0] = fmaxf(mx2[0], __shfl_xor_sync(0xffffffffu, mx2[0], off));
        mx2[1] = fmaxf(mx2[1], __shfl_xor_sync(0xffffffffu, mx2[1], off));
    }
    float l[2] = {0.f, 0.f}, l2[2] = {0.f, 0.f};
    #pragma unroll
    for (int j = 0; j < 10; j++)
        #pragma unroll
        for (int e = 0; e < 4; e++) {
            float p = __expf(s[j][e] - mx[e >> 1]);
            s[j][e] = p;
            l[e >> 1] += p;
        }
    #pragma unroll
    for (int j = 10; j < 12; j++)
        #pragma unroll
        for (int e = 0; e < 4; e++) {
            float p = __expf(s[j][e] - mx2[e >> 1]);
            s[j][e] = p;
            l2[e >> 1] += p;
        }
    #pragma unroll
    for (int off = 1; off <= 2; off <<= 1) {
        l[0]  += __shfl_xor_sync(0xffffffffu, l[0],  off);
        l[1]  += __shfl_xor_sync(0xffffffffu, l[1],  off);
        l2[0] += __shfl_xor_sync(0xffffffffu, l2[0], off);
        l2[1] += __shfl_xor_sync(0xffffffffu, l2[1], off);
    }
    float inv[2], inv2[2];
    inv[0] = 1.f / l[0];
    inv[1] = 1.f / l[1];
    inv2[0] = ipOn ? 1.f / l2[0] : 0.f;
    inv2[1] = ipOn ? 1.f / l2[1] : 0.f;
    #pragma unroll
    for (int j = 0; j < 10; j++)
        #pragma unroll
        for (int e = 0; e < 4; e++) s[j][e] *= inv[e >> 1];
    #pragma unroll
    for (int j = 10; j < 12; j++)
        #pragma unroll
        for (int e = 0; e < 4; e++) s[j][e] *= inv2[e >> 1];

    const uint32_t vtbase = smb + OFF_VHI
        + (uint32_t)((((lane >> 3) & 1) * 8 + (lane & 7)) * KROW + ((lane >> 4) & 1) * 16);
    float out[8][4];
    #pragma unroll
    for (int d = 0; d < 8; d++)
        #pragma unroll
        for (int e = 0; e < 4; e++) out[d][e] = 0.f;

    #pragma unroll
    for (int kk = 0; kk < 6; kk++) {
        uint32_t ah[4], al[4];
        #pragma unroll
        for (int r = 0; r < 4; r++) {
            const int t = 2 * kk + (r >> 1);
            const int pi = (r & 1) * 2;
            float v0 = s[t][pi], v1 = s[t][pi + 1];
            __nv_bfloat16 h0 = __float2bfloat16(v0);
            __nv_bfloat16 h1 = __float2bfloat16(v1);
            __nv_bfloat162 hh; hh.x = h0; hh.y = h1;
            ah[r] = *reinterpret_cast<uint32_t*>(&hh);
            al[r] = pack_bf16x2(v0 - __bfloat162float(h0), v1 - __bfloat162float(h1));
        }
        #pragma unroll
        for (int d = 0; d < 4; d++) {
            uint32_t Vh[4], Vl[4];
            ldsm_x4_t(Vh, vtbase + kk * 16 * KROW + d * 32);
            ldsm_x4_t(Vl, vtbase + (OFF_VLO - OFF_VHI) + kk * 16 * KROW + d * 32);
            #pragma unroll
            for (int half = 0; half < 2; half++) {
                const int j = 2 * d + half, hh = half * 2;
                mma16816(out[j], ah, Vh[hh], Vh[hh + 1]);
                mma16816(out[j], ah, Vl[hh], Vl[hh + 1]);
                mma16816(out[j], al, Vh[hh], Vh[hh + 1]);
            }
        }
    }

    const int g = lane >> 2;
    const long row0 = (long)b * SQ + rowBase + m0 + g;
    #pragma unroll
    for (int d = 0; d < 8; d++) {
        const int col = h * 64 + d * 8 + tig * 2;
        #pragma unroll
        for (int rr = 0; rr < 2; rr++) {
            float v0 = out[d][rr * 2 + 0], v1 = out[d][rr * 2 + 1];
            long o = (row0 + rr * 8) * HIDDEN + col;
            __nv_bfloat16 h0 = __float2bfloat16(v0);
            __nv_bfloat16 h1 = __float2bfloat16(v1);
            __nv_bfloat162 hh; hh.x = h0; hh.y = h1;
            *(uint32_t*)(ohi + o) = *reinterpret_cast<uint32_t*>(&hh);
            *(uint32_t*)(olo + o) = pack_bf16x2(
                v0 - __bfloat162float(h0), v1 - __bfloat162float(h1));
        }
    }
}

// ============================================================================
// Launcher
// ============================================================================
extern "C" void kernel_launch(void* const* d_in, const int* in_sizes, int n_in,
                              void* d_out, int out_size)
{
    const float* hidden = (const float*)d_in[0];
    const float* enc    = (const float*)d_in[1];
    const float* Wq     = (const float*)d_in[2];
    const float* Wk     = (const float*)d_in[3];
    const float* Wv     = (const float*)d_in[4];
    const float* Wk_ip  = (const float*)d_in[5];
    const float* Wv_ip  = (const float*)d_in[6];
    const float* Wout   = (const float*)d_in[7];
    const float* b_out  = (const float*)d_in[8];
    float* out = (float*)d_out;

    static bool attr_set = false;
    if (!attr_set) {
        cudaFuncSetAttribute(hmma_gemm, cudaFuncAttributeMaxDynamicSharedMemorySize, SMEM_TOT);
        cudaFuncSetAttribute(hmma_gemm_qkv, cudaFuncAttributeMaxDynamicSharedMemorySize, SMEM_TOT);
        cudaFuncSetAttribute(attn_mma, cudaFuncAttributeMaxDynamicSharedMemorySize, SMEM_ATTN);
        attr_set = true;
    }

    __nv_bfloat16 *ahi, *alo, *qhi, *qlo, *ehi, *elo;
    __nv_bfloat16 *wqh, *wql, *wth, *wtl, *woh, *wol, *kvh, *kvl;
    float* pbuf;
    cudaGetSymbolAddress((void**)&ahi, g_ahi);
    cudaGetSymbolAddress((void**)&alo, g_alo);
    cudaGetSymbolAddress((void**)&qhi, g_qhi);
    cudaGetSymbolAddress((void**)&qlo, g_qlo);
    cudaGetSymbolAddress((void**)&ehi, g_ehi);
    cudaGetSymbolAddress((void**)&elo, g_elo);
    cudaGetSymbolAddress((void**)&wqh, g_wqT_hi);
    cudaGetSymbolAddress((void**)&wql, g_wqT_lo);
    cudaGetSymbolAddress((void**)&wth, g_wT_hi);
    cudaGetSymbolAddress((void**)&wtl, g_wT_lo);
    cudaGetSymbolAddress((void**)&woh, g_woutT_hi);
    cudaGetSymbolAddress((void**)&wol, g_woutT_lo);
    cudaGetSymbolAddress((void**)&kvh, g_kvhi);
    cudaGetSymbolAddress((void**)&kvl, g_kvlo);
    cudaGetSymbolAddress((void**)&pbuf, g_part);

    const int M_big = NB * SQ;  // 16384
    const long WSLAB = (long)HIDDEN * CROSS;

    // 1) activation splits
    {
        int n4 = M_big * HIDDEN / 4;
        split_kernel<<<(n4 + 255) / 256, 256>>>(hidden, ahi, alo, n4);
    }
    {
        int n4 = NB * ENC * CROSS / 4;
        split_kernel<<<(n4 + 255) / 256, 256>>>(enc, ehi, elo, n4);
    }

    // 2) all weight transposes+splits in one launch
    {
        TSArgs t;
        t.src[0] = Wq;    t.dhi[0] = wqh;             t.dlo[0] = wql;             t.K[0] = HIDDEN;
        t.src[1] = Wk;    t.dhi[1] = wth + 0 * WSLAB; t.dlo[1] = wtl + 0 * WSLAB; t.K[1] = CROSS;
        t.src[2] = Wv;    t.dhi[2] = wth + 1 * WSLAB; t.dlo[2] = wtl + 1 * WSLAB; t.K[2] = CROSS;
        t.src[3] = Wk_ip; t.dhi[3] = wth + 2 * WSLAB; t.dlo[3] = wtl + 2 * WSLAB; t.K[3] = CROSS;
        t.src[4] = Wv_ip; t.dhi[4] = wth + 3 * WSLAB; t.dlo[4] = wtl + 3 * WSLAB; t.K[4] = CROSS;
        t.src[5] = Wout;  t.dhi[5] = woh;             t.dlo[5] = wol;             t.K[5] = HIDDEN;
        transpose_split_all<<<dim3(HIDDEN / 32, CROSS / 32, 6), dim3(32, 8)>>>(t);
    }

    // 3) merged Q projection + packed split-K kv projections (1920 CTAs)
    {
        QKVArgs a;
        a.ahi = ahi; a.alo = alo; a.ehi = ehi; a.elo = elo;
        a.wqh = wqh; a.wql = wql; a.wth = wth; a.wtl = wtl;
        a.qhi = qhi; a.qlo = qlo; a.pbuf = pbuf;
        hmma_gemm_qkv<<<1920, 256, SMEM_TOT>>>(a);
    }

    // 4) reduce split-K partials -> kv bf16 hi/lo
    {
        long n4 = PART_STRIDE / 4;
        reduce_split_kv<<<(int)((n4 + 255) / 256), 256>>>(pbuf, kvh, kvl);
    }

    // 5) HMMA attention -> hs bf16 hi/lo (reuses ahi/alo)
    attn_mma<<<dim3(SQ / 128, NHEADS, NB), 256, SMEM_ATTN>>>(qhi, qlo, kvh, kvl, ahi, alo);

    // 6) out = hs @ Wout + b_out + residual (fp32)
    {
        GemmArgs a = {ahi, alo, woh, wol, out, M_big, HIDDEN, HIDDEN, b_out, hidden};
        hmma_gemm<<<dim3(HIDDEN / 128, M_big / 128, 1), 256, SMEM_TOT>>>(a);
    }
}

// round 10
// speedup vs baseline: 1.4343x; 1.3282x over previous
#include <cuda_runtime.h>
#include <cuda_fp16.h>
#include <cstdint>

#define NHEADS 20
#define HEAD_DIM 64
#define HIDDEN 1280
#define CROSS 2048
#define NB 4
#define SQ 4096
#define TXT 77
#define NTOK 4
#define ENC (TXT + NTOK)

// ============================================================================
// PTX helpers (baseline-family only: mma.sync / ldmatrix / cp.async)
// ============================================================================
__device__ __forceinline__ uint32_t smem_to_u32(const void* smem_ptr) {
    uint32_t addr;
    asm("{ .reg .u64 tmp; cvta.to.shared.u64 tmp, %1; cvt.u32.u64 %0, tmp; }"
        : "=r"(addr) : "l"(smem_ptr));
    return addr;
}

__device__ __forceinline__ void cp_async16(uint32_t dst, const void* src, int bytes) {
    asm volatile("cp.async.cg.shared.global [%0], [%1], 16, %2;"
                 :: "r"(dst), "l"(src), "r"(bytes));
}
#define CP_COMMIT() asm volatile("cp.async.commit_group;" ::: "memory")
#define CP_WAIT(N)  asm volatile("cp.async.wait_group %0;" :: "n"(N) : "memory")

__device__ __forceinline__ void ldsm_x4(uint32_t* r, uint32_t a) {
    asm volatile("ldmatrix.sync.aligned.m8n8.x4.shared.b16 {%0,%1,%2,%3}, [%4];"
                 : "=r"(r[0]), "=r"(r[1]), "=r"(r[2]), "=r"(r[3]) : "r"(a));
}

__device__ __forceinline__ void ldsm_x4_t(uint32_t* r, uint32_t a) {
    asm volatile("ldmatrix.sync.aligned.m8n8.x4.trans.shared.b16 {%0,%1,%2,%3}, [%4];"
                 : "=r"(r[0]), "=r"(r[1]), "=r"(r[2]), "=r"(r[3]) : "r"(a));
}

// f16 x f16 -> f32 MMA
__device__ __forceinline__ void mma16816(float* c, const uint32_t* a,
                                         uint32_t b0, uint32_t b1) {
    asm volatile(
        "mma.sync.aligned.m16n8k16.row.col.f32.f16.f16.f32 "
        "{%0,%1,%2,%3},{%4,%5,%6,%7},{%8,%9},{%0,%1,%2,%3};"
        : "+f"(c[0]), "+f"(c[1]), "+f"(c[2]), "+f"(c[3])
        : "r"(a[0]), "r"(a[1]), "r"(a[2]), "r"(a[3]), "r"(b0), "r"(b1));
}

__device__ __forceinline__ uint32_t pack_half2(float a, float b) {
    __half2 t;
    t.x = __float2half(a);
    t.y = __float2half(b);
    return *reinterpret_cast<uint32_t*>(&t);
}

// ============================================================================
// Scratch (static device allocations)
// ============================================================================
#define PART_STRIDE ((long)16 * TXT * HIDDEN)   // floats per split-K partial

__device__ __half g_ahi[NB * SQ * HIDDEN];            // hidden-hi, then hs-hi
__device__ __half g_qhi[NB * SQ * HIDDEN];
__device__ __half g_ehi[NB * ENC * CROSS];
__device__ __half g_wqT_hi[HIDDEN * HIDDEN];
__device__ __half g_wqT_lo[HIDDEN * HIDDEN];
__device__ __half g_wT_hi[4 * HIDDEN * CROSS];
__device__ __half g_wT_lo[4 * HIDDEN * CROSS];
__device__ __half g_woutT_hi[HIDDEN * HIDDEN];
__device__ __half g_woutT_lo[HIDDEN * HIDDEN];
__device__ __half g_kvhi[4 * NB * TXT * HIDDEN];      // k,v,ipk,ipv
__device__ __half g_kvlo[4 * NB * TXT * HIDDEN];
__device__ float g_part[8 * 16 * TXT * HIDDEN];       // split-K partials

// ============================================================================
// fp32 -> fp16 hi-only split (activations)
// ============================================================================
__global__ __launch_bounds__(256)
void split_hi_kernel(const float* __restrict__ in, __half* __restrict__ hi, int n4)
{
    int i = blockIdx.x * blockDim.x + threadIdx.x;
    if (i >= n4) return;
    float4 x = ((const float4*)in)[i];
    ((uint2*)hi)[i] = make_uint2(pack_half2(x.x, x.y), pack_half2(x.z, x.w));
}

// ============================================================================
// Merged transpose + fp16 hi/lo split of all 6 weights (grid.z selects weight).
// ============================================================================
struct TSArgs {
    const float* src[6];
    __half* dhi[6];
    __half* dlo[6];
    int K[6];
};

__global__ __launch_bounds__(256)
void transpose_split_all(TSArgs args)
{
    const int w = blockIdx.z;
    const int K = args.K[w];
    const int k0 = blockIdx.y * 32;
    if (k0 >= K) return;
    const float* in = args.src[w];
    __half* ohi = args.dhi[w];
    __half* olo = args.dlo[w];

    __shared__ float t[32][33];
    const int tx = threadIdx.x, ty = threadIdx.y;
    const int n0 = blockIdx.x * 32;
    #pragma unroll
    for (int j = ty; j < 32; j += 8)
        t[j][tx] = in[(long)(k0 + j) * HIDDEN + n0 + tx];
    __syncthreads();
    #pragma unroll
    for (int j = ty; j < 32; j += 8) {
        float x = t[tx][j];
        __half h = __float2half(x);
        long o = (long)(n0 + j) * K + k0 + tx;
        ohi[o] = h;
        olo[o] = __float2half(x - __half2float(h));
    }
}

// ============================================================================
// Shared GEMM pieces: CTA 128x128x32, 8 warps, warp 32x64, cp.async double
// buffer. fp16 2-term split: acc += Ah*Bh + Ah*Bl (A hi-only).
// ============================================================================
#define LDS_ROW 80
#define STGBUF  30720            // A(10240) + Bh(10240) + Bl(10240)
#define OFF_A   0
#define OFF_BH  10240
#define OFF_BL  20480
#define SMEM_TOT 61440

// Interleaved per-accumulator 2-term compute (do NOT burst-reorder; see R8).
__device__ __forceinline__ void gemm_stage_compute(
    uint32_t base, uint32_t aoffs, uint32_t boffs, float acc[2][8][4])
{
    const uint32_t aA  = base + OFF_A;
    const uint32_t bHi = base + OFF_BH;
    const uint32_t bLo = base + OFF_BL;
    #pragma unroll
    for (int ks = 0; ks < 2; ks++) {
        uint32_t Ah[2][4];
        #pragma unroll
        for (int mi = 0; mi < 2; mi++)
            ldsm_x4(Ah[mi], aA + aoffs + mi * 16 * LDS_ROW + ks * 32);
        #pragma unroll
        for (int half = 0; half < 2; half++) {
            uint32_t Bh[2][4], Bl[2][4];
            #pragma unroll
            for (int nn = 0; nn < 2; nn++) {
                const uint32_t bo = boffs + (half * 2 + nn) * 16 * LDS_ROW + ks * 32;
                ldsm_x4(Bh[nn], bHi + bo);
                ldsm_x4(Bl[nn], bLo + bo);
            }
            #pragma unroll
            for (int mi = 0; mi < 2; mi++) {
                #pragma unroll
                for (int j4 = 0; j4 < 4; j4++) {
                    const int ni = j4 >> 1, h = (j4 & 1) * 2;
                    float* a = acc[mi][half * 4 + j4];
                    mma16816(a, Ah[mi], Bh[ni][h], Bh[ni][h + 1]);
                    mma16816(a, Ah[mi], Bl[ni][h], Bl[ni][h + 1]);
                }
            }
        }
    }
}

// kv packed-row map: parts 0-2 text K (4x77 rows), 3-5 text V, 6 ipK (16), 7 ipV.
__device__ __forceinline__ bool kv_map(int part, int r, long& aRow, long& cRow)
{
    aRow = 0; cRow = 0;
    if (part < 6) {
        int R = (part % 3) * 128 + r;
        if (R >= 4 * TXT) return false;
        int batch = R / TXT, rr = R - batch * TXT;
        aRow = (long)batch * ENC + rr;
        cRow = (long)(((part < 3 ? 0 : 1) * 4 + batch) * TXT + rr);
        return true;
    } else {
        if (r >= 16) return false;
        int batch = r >> 2, rr = r & 3;
        aRow = (long)batch * ENC + TXT + rr;
        cRow = (long)(((part == 6 ? 2 : 3) * 4 + batch) * TXT + rr);
        return true;
    }
}

// ============================================================================
// Merged Q-projection + packed split-K kv-projection GEMM.
// 1-D grid of 1920 CTAs: bid < 1280 -> Q tile (40 stages),
// bid >= 1280 -> kv tile (8 stages, backfills Q tail wave).
// ============================================================================
struct QKVArgs {
    const __half *ahi, *ehi;
    const __half *wqh, *wql, *wth, *wtl;
    __half *qhi;
    float* pbuf;
};

__global__ __launch_bounds__(256, 2)
void hmma_gemm_qkv(QKVArgs args)
{
    extern __shared__ __align__(16) char smx[];
    const uint32_t smb = smem_to_u32(smx);
    const int tid = threadIdx.x;
    const int bid = blockIdx.x;
    const bool isQ = bid < 1280;

    const int lr0 = tid >> 2;
    const int cch = tid & 3;

    const __half *Ahi, *Bhi, *Blo;
    int K, NS, kBase, colBase, rowBase = 0, part = 0, split = 0;
    int aRow[2];
    int aBytes[2];

    if (isQ) {
        rowBase = (bid / 10) * 128;
        colBase = (bid % 10) * 128;
        Ahi = args.ahi;
        Bhi = args.wqh; Blo = args.wql;
        K = HIDDEN; NS = 40; kBase = 0;
        aRow[0] = rowBase + lr0;
        aRow[1] = rowBase + lr0 + 64;
        aBytes[0] = 16; aBytes[1] = 16;
    } else {
        const int t = bid - 1280;
        colBase = (t % 10) * 128;
        part = (t / 10) & 7;
        split = t / 80;
        const int gemm = part < 3 ? 0 : (part < 6 ? 1 : (part == 6 ? 2 : 3));
        Ahi = args.ehi;
        Bhi = args.wth + (long)gemm * HIDDEN * CROSS;
        Blo = args.wtl + (long)gemm * HIDDEN * CROSS;
        K = CROSS; NS = 8; kBase = split * 256;
        long ar, cr;
        aBytes[0] = kv_map(part, lr0, ar, cr) ? 16 : 0;      aRow[0] = (int)ar;
        aBytes[1] = kv_map(part, lr0 + 64, ar, cr) ? 16 : 0; aRow[1] = (int)ar;
    }

    const int warp = tid >> 5, lane = tid & 31;
    const int wm = warp >> 1, wn = warp & 1;
    const int m0 = wm * 32, n0 = wn * 64;

    const uint32_t aoffs = (uint32_t)((m0 + (lane & 15)) * LDS_ROW + (lane >> 4) * 16);
    const uint32_t boffs = (uint32_t)((n0 + ((lane >> 4) & 1) * 8 + (lane & 7)) * LDS_ROW
                                      + ((lane >> 3) & 1) * 16);

    float acc[2][8][4];
    #pragma unroll
    for (int mi = 0; mi < 2; mi++)
        #pragma unroll
        for (int nj = 0; nj < 8; nj++)
            #pragma unroll
            for (int t = 0; t < 4; t++) acc[mi][nj][t] = 0.f;

    auto load_stage = [&](int s) {
        const int b = s & 1;
        const int k0 = kBase + (s << 5);
        #pragma unroll
        for (int i = 0; i < 2; i++) {
            const int r = lr0 + i * 64;
            uint32_t d = smb + (uint32_t)(b * STGBUF + r * LDS_ROW + cch * 16);
            long go = (long)aRow[i] * K + k0 + cch * 8;
            cp_async16(d + OFF_A, Ahi + go, aBytes[i]);
            long gb = (long)(colBase + r) * K + k0 + cch * 8;
            cp_async16(d + OFF_BH, Bhi + gb, 16);
            cp_async16(d + OFF_BL, Blo + gb, 16);
        }
        CP_COMMIT();
    };

    load_stage(0);
    for (int s = 0; s < NS; ++s) {
        if (s + 1 < NS) {
            load_stage(s + 1);
            CP_WAIT(1);
        } else {
            CP_WAIT(0);
        }
        __syncthreads();
        gemm_stage_compute(smb + (s & 1) * STGBUF, aoffs, boffs, acc);
        __syncthreads();
    }

    // Epilogue
    const int g = lane >> 2, tig = lane & 3;
    if (isQ) {
        #pragma unroll
        for (int mi = 0; mi < 2; mi++) {
            #pragma unroll
            for (int nj = 0; nj < 8; nj++) {
                const int r0 = rowBase + m0 + mi * 16 + g;
                const int col = colBase + n0 + nj * 8 + tig * 2;
                #pragma unroll
                for (int rr = 0; rr < 2; rr++) {
                    long o = (long)(r0 + rr * 8) * HIDDEN + col;
                    *(uint32_t*)(args.qhi + o) =
                        pack_half2(acc[mi][nj][rr * 2 + 0], acc[mi][nj][rr * 2 + 1]);
                }
            }
        }
    } else {
        float* pout = args.pbuf + (long)split * PART_STRIDE;
        #pragma unroll
        for (int mi = 0; mi < 2; mi++) {
            #pragma unroll
            for (int nj = 0; nj < 8; nj++) {
                const int r0 = m0 + mi * 16 + g;
                const int col = colBase + n0 + nj * 8 + tig * 2;
                long aR, cR;
                if (kv_map(part, r0, aR, cR))
                    *(float2*)(pout + cR * HIDDEN + col) =
                        make_float2(acc[mi][nj][0], acc[mi][nj][1]);
                if (kv_map(part, r0 + 8, aR, cR))
                    *(float2*)(pout + cR * HIDDEN + col) =
                        make_float2(acc[mi][nj][2], acc[mi][nj][3]);
            }
        }
    }
}

// ============================================================================
// Out-projection GEMM (fp16 2-term, fused bias+resid).
// ============================================================================
struct GemmArgs {
    const __half *Ahi, *Bhi, *Blo;
    float* C;
    int K, ldc;
    const float *bias, *resid;
};

__global__ __launch_bounds__(256, 2)
void hmma_gemm(GemmArgs args)
{
    extern __shared__ __align__(16) char smx[];
    const uint32_t smb = smem_to_u32(smx);
    const int tid = threadIdx.x;

    const __half* Ahi = args.Ahi;
    const __half* Bhi = args.Bhi;
    const __half* Blo = args.Blo;
    const int K = args.K, ldc = args.ldc;

    const int rowBase = blockIdx.y * 128;
    const int colBase = blockIdx.x * 128;
    const int NS = K >> 5;
    const int lr0 = tid >> 2;
    const int cch = tid & 3;

    const int warp = tid >> 5, lane = tid & 31;
    const int wm = warp >> 1, wn = warp & 1;
    const int m0 = wm * 32, n0 = wn * 64;

    const uint32_t aoffs = (uint32_t)((m0 + (lane & 15)) * LDS_ROW + (lane >> 4) * 16);
    const uint32_t boffs = (uint32_t)((n0 + ((lane >> 4) & 1) * 8 + (lane & 7)) * LDS_ROW
                                      + ((lane >> 3) & 1) * 16);

    float acc[2][8][4];
    #pragma unroll
    for (int mi = 0; mi < 2; mi++)
        #pragma unroll
        for (int nj = 0; nj < 8; nj++)
            #pragma unroll
            for (int t = 0; t < 4; t++) acc[mi][nj][t] = 0.f;

    auto load_stage = [&](int s) {
        const int b = s & 1;
        const long k0 = (long)s << 5;
        #pragma unroll
        for (int i = 0; i < 2; i++) {
            const int r = lr0 + i * 64;
            uint32_t d = smb + (uint32_t)(b * STGBUF + r * LDS_ROW + cch * 16);
            long go = (long)(rowBase + r) * K + k0 + cch * 8;
            cp_async16(d + OFF_A, Ahi + go, 16);
            long gb = (long)(colBase + r) * K + k0 + cch * 8;
            cp_async16(d + OFF_BH, Bhi + gb, 16);
            cp_async16(d + OFF_BL, Blo + gb, 16);
        }
        CP_COMMIT();
    };

    load_stage(0);
    for (int s = 0; s < NS; ++s) {
        if (s + 1 < NS) {
            load_stage(s + 1);
            CP_WAIT(1);
        } else {
            CP_WAIT(0);
        }
        __syncthreads();
        gemm_stage_compute(smb + (s & 1) * STGBUF, aoffs, boffs, acc);
        __syncthreads();
    }

    // Epilogue: fp32 + bias + residual
    const int g = lane >> 2, tig = lane & 3;
    const float* bias = args.bias;
    const float* resid = args.resid;
    #pragma unroll
    for (int mi = 0; mi < 2; mi++) {
        #pragma unroll
        for (int nj = 0; nj < 8; nj++) {
            const int r0 = rowBase + m0 + mi * 16 + g;
            const int col = colBase + n0 + nj * 8 + tig * 2;
            float2 v0 = make_float2(acc[mi][nj][0], acc[mi][nj][1]);
            float2 v1 = make_float2(acc[mi][nj][2], acc[mi][nj][3]);
            const float2 bi = *(const float2*)(bias + col);
            v0.x += bi.x; v0.y += bi.y;
            v1.x += bi.x; v1.y += bi.y;
            const float2 rr0 = *(const float2*)(resid + (long)r0 * ldc + col);
            v0.x += rr0.x; v0.y += rr0.y;
            const float2 rr1 = *(const float2*)(resid + (long)(r0 + 8) * ldc + col);
            v1.x += rr1.x; v1.y += rr1.y;
            *(float2*)(args.C + (long)r0 * ldc + col)       = v0;
            *(float2*)(args.C + (long)(r0 + 8) * ldc + col) = v1;
        }
    }
}

// Sum 8 split-K partials + fp16 hi/lo split (kv is B-side of attention).
__global__ __launch_bounds__(256)
void reduce_split_kv(const float* __restrict__ part,
                     __half* __restrict__ hi, __half* __restrict__ lo)
{
    const long n4 = PART_STRIDE / 4;
    long i = (long)blockIdx.x * 256 + threadIdx.x;
    if (i >= n4) return;
    const float4* p4 = (const float4*)part;
    float4 s = p4[i];
    #pragma unroll
    for (int k = 1; k < 8; k++) {
        float4 t = p4[i + (long)k * n4];
        s.x += t.x; s.y += t.y; s.z += t.z; s.w += t.w;
    }
    __half h0 = __float2half(s.x);
    __half h1 = __float2half(s.y);
    __half h2 = __float2half(s.z);
    __half h3 = __float2half(s.w);
    __half2 hA; hA.x = h0; hA.y = h1;
    __half2 hB; hB.x = h2; hB.y = h3;
    ((uint2*)hi)[i] = make_uint2(*reinterpret_cast<uint32_t*>(&hA),
                                 *reinterpret_cast<uint32_t*>(&hB));
    uint32_t l01 = pack_half2(s.x - __half2float(h0), s.y - __half2float(h1));
    uint32_t l23 = pack_half2(s.z - __half2float(h2), s.w - __half2float(h3));
    ((uint2*)lo)[i] = make_uint2(l01, l23);
}

// ============================================================================
// HMMA flash attention: CTA = 128 q-rows x 96 keys (77 text + pad + 4 ip @80).
// 8 warps, warp = 16 rows. fp16 2-term (Q hi-only, K/V hi+lo).
// Writes hs as fp16 hi-only.
// ============================================================================
#define AROW 144
#define KROW 144
#define OFF_Q  0
#define OFF_KH (128 * AROW)                 // 18432
#define OFF_KL (OFF_KH + 96 * KROW)         // 32256
#define OFF_VH (OFF_KL + 96 * KROW)         // 46080
#define OFF_VL (OFF_VH + 96 * KROW)         // 59904
#define SMEM_ATTN (OFF_VL + 96 * KROW)      // 73728

__global__ __launch_bounds__(256)
void attn_mma(const __half* __restrict__ qhi,
              const __half* __restrict__ kvhi,
              const __half* __restrict__ kvlo,
              __half* __restrict__ ohi)
{
    extern __shared__ __align__(16) char smx[];
    const uint32_t smb = smem_to_u32(smx);
    const int tid = threadIdx.x;
    const int b = blockIdx.z, h = blockIdx.y;
    const int rowBase = blockIdx.x * 128;
    const long SLAB = (long)NB * TXT * HIDDEN;

    // Q tile: 128 rows x 64 dims, hi only
    #pragma unroll
    for (int i = 0; i < 4; i++) {
        int idx = tid + i * 256;
        int r = idx >> 3, c = idx & 7;
        long src = ((long)b * SQ + rowBase + r) * HIDDEN + h * 64 + c * 8;
        cp_async16(smb + OFF_Q + (uint32_t)(r * AROW + c * 16), qhi + src, 16);
    }
    // K tile (hi+lo): rows 0-76 text K, 80-83 ipK, rest zero
    #pragma unroll
    for (int i = 0; i < 3; i++) {
        int idx = tid + i * 256;
        int r = idx >> 3, c = idx & 7;
        int bytes = 0;
        long src = 0;
        if (r < TXT) {
            bytes = 16;
            src = (long)b * TXT * HIDDEN + (long)r * HIDDEN + h * 64 + c * 8;
        } else if (r >= 80 && r < 80 + NTOK) {
            bytes = 16;
            src = 2 * SLAB + (long)b * TXT * HIDDEN + (long)(r - 80) * HIDDEN + h * 64 + c * 8;
        }
        uint32_t d = smb + (uint32_t)(r * KROW + c * 16);
        cp_async16(d + OFF_KH, kvhi + src, bytes);
        cp_async16(d + OFF_KL, kvlo + src, bytes);
    }
    // V tile (hi+lo): rows 0-76 text V, 80-83 ipV, [key][dim]
    #pragma unroll
    for (int i = 0; i < 3; i++) {
        int idx = tid + i * 256;
        int r = idx >> 3, c = idx & 7;
        int bytes = 0;
        long src = 0;
        if (r < TXT) {
            bytes = 16;
            src = SLAB + (long)b * TXT * HIDDEN + (long)r * HIDDEN + h * 64 + c * 8;
        } else if (r >= 80 && r < 80 + NTOK) {
            bytes = 16;
            src = 3 * SLAB + (long)b * TXT * HIDDEN + (long)(r - 80) * HIDDEN + h * 64 + c * 8;
        }
        uint32_t d = smb + (uint32_t)(r * KROW + c * 16);
        cp_async16(d + OFF_VH, kvhi + src, bytes);
        cp_async16(d + OFF_VL, kvlo + src, bytes);
    }
    CP_COMMIT();
    CP_WAIT(0);
    __syncthreads();

    const int warp = tid >> 5, lane = tid & 31;
    const int m0 = warp * 16;
    const int tig = lane & 3;
    const uint32_t aoffs = smb + OFF_Q + (uint32_t)((m0 + (lane & 15)) * AROW + (lane >> 4) * 16);
    const uint32_t kbase = smb
        + (uint32_t)((((lane >> 4) & 1) * 8 + (lane & 7)) * KROW + ((lane >> 3) & 1) * 16);

    // S = Q K^T (12 n-tiles of 8 keys = 96)
    float s[12][4];
    #pragma unroll
    for (int j = 0; j < 12; j++)
        #pragma unroll
        for (int e = 0; e < 4; e++) s[j][e] = 0.f;

    #pragma unroll
    for (int ks = 0; ks < 4; ks++) {
        uint32_t Qh[4];
        ldsm_x4(Qh, aoffs + ks * 32);
        #pragma unroll
        for (int t = 0; t < 6; t++) {
            uint32_t Bh[4], Bl[4];
            ldsm_x4(Bh, kbase + OFF_KH + t * 16 * KROW + ks * 32);
            ldsm_x4(Bl, kbase + OFF_KL + t * 16 * KROW + ks * 32);
            #pragma unroll
            for (int half = 0; half < 2; half++) {
                const int j = 2 * t + half, hh = half * 2;
                mma16816(s[j], Qh, Bh[hh], Bh[hh + 1]);
                mma16816(s[j], Qh, Bl[hh], Bl[hh + 1]);
            }
        }
    }

    // scale + mask + dual softmax
    const bool ipOn = (b & 1);
    float mx[2]  = {-1e30f, -1e30f};
    float mx2[2] = {-1e30f, -1e30f};
    #pragma unroll
    for (int j = 0; j < 10; j++)
        #pragma unroll
        for (int e = 0; e < 4; e++) {
            int col = j * 8 + tig * 2 + (e & 1);
            float v = s[j][e] * 0.125f;
            s[j][e] = (col < TXT) ? v : -1e30f;
            mx[e >> 1] = fmaxf(mx[e >> 1], s[j][e]);
        }
    #pragma unroll
    for (int j = 10; j < 12; j++)
        #pragma unroll
        for (int e = 0; e < 4; e++) {
            int col = j * 8 + tig * 2 + (e & 1);
            float v = s[j][e] * 0.125f;
            s[j][e] = (col >= 80 && col < 80 + NTOK) ? v : -1e30f;
            mx2[e >> 1] = fmaxf(mx2[e >> 1], s[j][e]);
        }
    #pragma unroll
    for (int off = 1; off <= 2; off <<= 1) {
        mx[0]  = fmaxf(mx[0],  __shfl_xor_sync(0xffffffffu, mx[0],  off));
        mx[1]  = fmaxf(mx[1],  __shfl_xor_sync(0xffffffffu, mx[1],  off));
        mx2[0] = fmaxf(mx2[0], __shfl_xor_sync(0xffffffffu, mx2[0], off));
        mx2[1] = fmaxf(mx2[1], __shfl_xor_sync(0xffffffffu, mx2[1], off));
    }
    float l[2] = {0.f, 0.f}, l2[2] = {0.f, 0.f};
    #pragma unroll
    for (int j = 0; j < 10; j++)
        #pragma unroll
        for (int e = 0; e < 4; e++) {
            float p = __expf(s[j][e] - mx[e >> 1]);
            s[j][e] = p;
            l[e >> 1] += p;
        }
    #pragma unroll
    for (int j = 10; j < 12; j++)
        #pragma unroll
        for (int e = 0; e < 4; e++) {
            float p = __expf(s[j][e] - mx2[e >> 1]);
            s[j][e] = p;
            l2[e >> 1] += p;
        }
    #pragma unroll
    for (int off = 1; off <= 2; off <<= 1) {
        l[0]  += __shfl_xor_sync(0xffffffffu, l[0],  off);
        l[1]  += __shfl_xor_sync(0xffffffffu, l[1],  off);
        l2[0] += __shfl_xor_sync(0xffffffffu, l2[0], off);
        l2[1] += __shfl_xor_sync(0xffffffffu, l2[1], off);
    }
    float inv[2], inv2[2];
    inv[0] = 1.f / l[0];
    inv[1] = 1.f / l[1];
    inv2[0] = ipOn ? 1.f / l2[0] : 0.f;
    inv2[1] = ipOn ? 1.f / l2[1] : 0.f;
    #pragma unroll
    for (int j = 0; j < 10; j++)
        #pragma unroll
        for (int e = 0; e < 4; e++) s[j][e] *= inv[e >> 1];
    #pragma unroll
    for (int j = 10; j < 12; j++)
        #pragma unroll
        for (int e = 0; e < 4; e++) s[j][e] *= inv2[e >> 1];

    // PV via ldsm.trans on V[key][dim] (P hi-only, V hi+lo)
    const uint32_t vtbase = smb
        + (uint32_t)((((lane >> 3) & 1) * 8 + (lane & 7)) * KROW + ((lane >> 4) & 1) * 16);
    float out[8][4];
    #pragma unroll
    for (int d = 0; d < 8; d++)
        #pragma unroll
        for (int e = 0; e < 4; e++) out[d][e] = 0.f;

    #pragma unroll
    for (int kk = 0; kk < 6; kk++) {
        uint32_t ah[4];
        #pragma unroll
        for (int r = 0; r < 4; r++) {
            const int t = 2 * kk + (r >> 1);
            const int pi = (r & 1) * 2;
            ah[r] = pack_half2(s[t][pi], s[t][pi + 1]);
        }
        #pragma unroll
        for (int d = 0; d < 4; d++) {
            uint32_t Vh[4], Vl[4];
            ldsm_x4_t(Vh, vtbase + OFF_VH + kk * 16 * KROW + d * 32);
            ldsm_x4_t(Vl, vtbase + OFF_VL + kk * 16 * KROW + d * 32);
            #pragma unroll
            for (int half = 0; half < 2; half++) {
                const int j = 2 * d + half, hh = half * 2;
                mma16816(out[j], ah, Vh[hh], Vh[hh + 1]);
                mma16816(out[j], ah, Vl[hh], Vl[hh + 1]);
            }
        }
    }

    // write hs fp16 hi-only
    const int g = lane >> 2;
    const long row0 = (long)b * SQ + rowBase + m0 + g;
    #pragma unroll
    for (int d = 0; d < 8; d++) {
        const int col = h * 64 + d * 8 + tig * 2;
        #pragma unroll
        for (int rr = 0; rr < 2; rr++) {
            long o = (row0 + rr * 8) * HIDDEN + col;
            *(uint32_t*)(ohi + o) = pack_half2(out[d][rr * 2 + 0], out[d][rr * 2 + 1]);
        }
    }
}

// ============================================================================
// Launcher
// ============================================================================
extern "C" void kernel_launch(void* const* d_in, const int* in_sizes, int n_in,
                              void* d_out, int out_size)
{
    const float* hidden = (const float*)d_in[0];
    const float* enc    = (const float*)d_in[1];
    const float* Wq     = (const float*)d_in[2];
    const float* Wk     = (const float*)d_in[3];
    const float* Wv     = (const float*)d_in[4];
    const float* Wk_ip  = (const float*)d_in[5];
    const float* Wv_ip  = (const float*)d_in[6];
    const float* Wout   = (const float*)d_in[7];
    const float* b_out  = (const float*)d_in[8];
    float* out = (float*)d_out;

    static bool attr_set = false;
    if (!attr_set) {
        cudaFuncSetAttribute(hmma_gemm, cudaFuncAttributeMaxDynamicSharedMemorySize, SMEM_TOT);
        cudaFuncSetAttribute(hmma_gemm_qkv, cudaFuncAttributeMaxDynamicSharedMemorySize, SMEM_TOT);
        cudaFuncSetAttribute(attn_mma, cudaFuncAttributeMaxDynamicSharedMemorySize, SMEM_ATTN);
        attr_set = true;
    }

    __half *ahi, *qhi, *ehi;
    __half *wqh, *wql, *wth, *wtl, *woh, *wol, *kvh, *kvl;
    float* pbuf;
    cudaGetSymbolAddress((void**)&ahi, g_ahi);
    cudaGetSymbolAddress((void**)&qhi, g_qhi);
    cudaGetSymbolAddress((void**)&ehi, g_ehi);
    cudaGetSymbolAddress((void**)&wqh, g_wqT_hi);
    cudaGetSymbolAddress((void**)&wql, g_wqT_lo);
    cudaGetSymbolAddress((void**)&wth, g_wT_hi);
    cudaGetSymbolAddress((void**)&wtl, g_wT_lo);
    cudaGetSymbolAddress((void**)&woh, g_woutT_hi);
    cudaGetSymbolAddress((void**)&wol, g_woutT_lo);
    cudaGetSymbolAddress((void**)&kvh, g_kvhi);
    cudaGetSymbolAddress((void**)&kvl, g_kvlo);
    cudaGetSymbolAddress((void**)&pbuf, g_part);

    const int M_big = NB * SQ;  // 16384
    const long WSLAB = (long)HIDDEN * CROSS;

    // 1) activation hi-splits
    {
        int n4 = M_big * HIDDEN / 4;
        split_hi_kernel<<<(n4 + 255) / 256, 256>>>(hidden, ahi, n4);
    }
    {
        int n4 = NB * ENC * CROSS / 4;
        split_hi_kernel<<<(n4 + 255) / 256, 256>>>(enc, ehi, n4);
    }

    // 2) all weight transposes+splits in one launch
    {
        TSArgs t;
        t.src[0] = Wq;    t.dhi[0] = wqh;             t.dlo[0] = wql;             t.K[0] = HIDDEN;
        t.src[1] = Wk;    t.dhi[1] = wth + 0 * WSLAB; t.dlo[1] = wtl + 0 * WSLAB; t.K[1] = CROSS;
        t.src[2] = Wv;    t.dhi[2] = wth + 1 * WSLAB; t.dlo[2] = wtl + 1 * WSLAB; t.K[2] = CROSS;
        t.src[3] = Wk_ip; t.dhi[3] = wth + 2 * WSLAB; t.dlo[3] = wtl + 2 * WSLAB; t.K[3] = CROSS;
        t.src[4] = Wv_ip; t.dhi[4] = wth + 3 * WSLAB; t.dlo[4] = wtl + 3 * WSLAB; t.K[4] = CROSS;
        t.src[5] = Wout;  t.dhi[5] = woh;             t.dlo[5] = wol;             t.K[5] = HIDDEN;
        transpose_split_all<<<dim3(HIDDEN / 32, CROSS / 32, 6), dim3(32, 8)>>>(t);
    }

    // 3) merged Q projection + packed split-K kv projections (1920 CTAs)
    {
        QKVArgs a;
        a.ahi = ahi; a.ehi = ehi;
        a.wqh = wqh; a.wql = wql; a.wth = wth; a.wtl = wtl;
        a.qhi = qhi; a.pbuf = pbuf;
        hmma_gemm_qkv<<<1920, 256, SMEM_TOT>>>(a);
    }

    // 4) reduce split-K partials -> kv fp16 hi/lo
    {
        long n4 = PART_STRIDE / 4;
        reduce_split_kv<<<(int)((n4 + 255) / 256), 256>>>(pbuf, kvh, kvl);
    }

    // 5) HMMA attention -> hs fp16 hi (reuses g_ahi)
    attn_mma<<<dim3(SQ / 128, NHEADS, NB), 256, SMEM_ATTN>>>(qhi, kvh, kvl, ahi);

    // 6) out = hs @ Wout + b_out + residual (fp32)
    {
        GemmArgs a = {ahi, woh, wol, out, HIDDEN, HIDDEN, b_out, hidden};
        hmma_gemm<<<dim3(HIDDEN / 128, M_big / 128, 1), 256, SMEM_TOT>>>(a);
    }
}

// round 11
// speedup vs baseline: 2.0244x; 1.4115x over previous
#include <cuda_runtime.h>
#include <cuda_fp16.h>
#include <cstdint>

#define NHEADS 20
#define HEAD_DIM 64
#define HIDDEN 1280
#define CROSS 2048
#define NB 4
#define SQ 4096
#define TXT 77
#define NTOK 4
#define ENC (TXT + NTOK)

// ============================================================================
// PTX helpers (baseline-family only: mma.sync / ldmatrix / cp.async)
// ============================================================================
__device__ __forceinline__ uint32_t smem_to_u32(const void* smem_ptr) {
    uint32_t addr;
    asm("{ .reg .u64 tmp; cvta.to.shared.u64 tmp, %1; cvt.u32.u64 %0, tmp; }"
        : "=r"(addr) : "l"(smem_ptr));
    return addr;
}

__device__ __forceinline__ void cp_async16(uint32_t dst, const void* src, int bytes) {
    asm volatile("cp.async.cg.shared.global [%0], [%1], 16, %2;"
                 :: "r"(dst), "l"(src), "r"(bytes));
}
#define CP_COMMIT() asm volatile("cp.async.commit_group;" ::: "memory")
#define CP_WAIT(N)  asm volatile("cp.async.wait_group %0;" :: "n"(N) : "memory")

__device__ __forceinline__ void ldsm_x4(uint32_t* r, uint32_t a) {
    asm volatile("ldmatrix.sync.aligned.m8n8.x4.shared.b16 {%0,%1,%2,%3}, [%4];"
                 : "=r"(r[0]), "=r"(r[1]), "=r"(r[2]), "=r"(r[3]) : "r"(a));
}

__device__ __forceinline__ void ldsm_x4_t(uint32_t* r, uint32_t a) {
    asm volatile("ldmatrix.sync.aligned.m8n8.x4.trans.shared.b16 {%0,%1,%2,%3}, [%4];"
                 : "=r"(r[0]), "=r"(r[1]), "=r"(r[2]), "=r"(r[3]) : "r"(a));
}

// f16 x f16 -> f32 MMA
__device__ __forceinline__ void mma16816(float* c, const uint32_t* a,
                                         uint32_t b0, uint32_t b1) {
    asm volatile(
        "mma.sync.aligned.m16n8k16.row.col.f32.f16.f16.f32 "
        "{%0,%1,%2,%3},{%4,%5,%6,%7},{%8,%9},{%0,%1,%2,%3};"
        : "+f"(c[0]), "+f"(c[1]), "+f"(c[2]), "+f"(c[3])
        : "r"(a[0]), "r"(a[1]), "r"(a[2]), "r"(a[3]), "r"(b0), "r"(b1));
}

__device__ __forceinline__ uint32_t pack_half2(float a, float b) {
    __half2 t;
    t.x = __float2half(a);
    t.y = __float2half(b);
    return *reinterpret_cast<uint32_t*>(&t);
}

// ============================================================================
// Scratch (static device allocations)
// ============================================================================
#define PART_STRIDE ((long)16 * TXT * HIDDEN)   // floats per split-K partial

__device__ __half g_ahi[NB * SQ * HIDDEN];            // hidden-hi, then hs-hi
__device__ __half g_qhi[NB * SQ * HIDDEN];
__device__ __half g_ehi[NB * ENC * CROSS];
__device__ __half g_wqT[HIDDEN * HIDDEN];
__device__ __half g_wT[4 * HIDDEN * CROSS];           // wk, wv, wkip, wvip (T)
__device__ __half g_woutT[HIDDEN * HIDDEN];
__device__ __half g_kv[4 * NB * TXT * HIDDEN];        // k,v,ipk,ipv
__device__ float g_part[8 * 16 * TXT * HIDDEN];       // split-K partials

// ============================================================================
// fp32 -> fp16 convert (activations)
// ============================================================================
__global__ __launch_bounds__(256)
void split_hi_kernel(const float* __restrict__ in, __half* __restrict__ hi, int n4)
{
    int i = blockIdx.x * blockDim.x + threadIdx.x;
    if (i >= n4) return;
    float4 x = ((const float4*)in)[i];
    ((uint2*)hi)[i] = make_uint2(pack_half2(x.x, x.y), pack_half2(x.z, x.w));
}

// ============================================================================
// Merged transpose + fp16 convert of all 6 weights (grid.z selects weight).
// ============================================================================
struct TSArgs {
    const float* src[6];
    __half* dst[6];
    int K[6];
};

__global__ __launch_bounds__(256)
void transpose_all(TSArgs args)
{
    const int w = blockIdx.z;
    const int K = args.K[w];
    const int k0 = blockIdx.y * 32;
    if (k0 >= K) return;
    const float* in = args.src[w];
    __half* dst = args.dst[w];

    __shared__ float t[32][33];
    const int tx = threadIdx.x, ty = threadIdx.y;
    const int n0 = blockIdx.x * 32;
    #pragma unroll
    for (int j = ty; j < 32; j += 8)
        t[j][tx] = in[(long)(k0 + j) * HIDDEN + n0 + tx];
    __syncthreads();
    #pragma unroll
    for (int j = ty; j < 32; j += 8)
        dst[(long)(n0 + j) * K + k0 + tx] = __float2half(t[tx][j]);
}

// ============================================================================
// Shared GEMM pieces: CTA 128x128x32, 8 warps, warp 32x64, cp.async double
// buffer, pure fp16 single-term.
// ============================================================================
#define LDS_ROW 80
#define STGBUF  20480            // A(10240) + B(10240)
#define OFF_A   0
#define OFF_B   10240
#define SMEM_TOT 40960

// Interleaved per-accumulator compute (do NOT burst-reorder; see R8).
__device__ __forceinline__ void gemm_stage_compute(
    uint32_t base, uint32_t aoffs, uint32_t boffs, float acc[2][8][4])
{
    const uint32_t aA = base + OFF_A;
    const uint32_t bB = base + OFF_B;
    #pragma unroll
    for (int ks = 0; ks < 2; ks++) {
        uint32_t Ah[2][4];
        #pragma unroll
        for (int mi = 0; mi < 2; mi++)
            ldsm_x4(Ah[mi], aA + aoffs + mi * 16 * LDS_ROW + ks * 32);
        #pragma unroll
        for (int half = 0; half < 2; half++) {
            uint32_t Bh[2][4];
            #pragma unroll
            for (int nn = 0; nn < 2; nn++)
                ldsm_x4(Bh[nn], bB + boffs + (half * 2 + nn) * 16 * LDS_ROW + ks * 32);
            #pragma unroll
            for (int mi = 0; mi < 2; mi++) {
                #pragma unroll
                for (int j4 = 0; j4 < 4; j4++) {
                    const int ni = j4 >> 1, h = (j4 & 1) * 2;
                    mma16816(acc[mi][half * 4 + j4], Ah[mi], Bh[ni][h], Bh[ni][h + 1]);
                }
            }
        }
    }
}

// kv packed-row map: parts 0-2 text K (4x77 rows), 3-5 text V, 6 ipK (16), 7 ipV.
__device__ __forceinline__ bool kv_map(int part, int r, long& aRow, long& cRow)
{
    aRow = 0; cRow = 0;
    if (part < 6) {
        int R = (part % 3) * 128 + r;
        if (R >= 4 * TXT) return false;
        int batch = R / TXT, rr = R - batch * TXT;
        aRow = (long)batch * ENC + rr;
        cRow = (long)(((part < 3 ? 0 : 1) * 4 + batch) * TXT + rr);
        return true;
    } else {
        if (r >= 16) return false;
        int batch = r >> 2, rr = r & 3;
        aRow = (long)batch * ENC + TXT + rr;
        cRow = (long)(((part == 6 ? 2 : 3) * 4 + batch) * TXT + rr);
        return true;
    }
}

// ============================================================================
// Merged Q-projection + packed split-K kv-projection GEMM.
// 1-D grid of 1920 CTAs: bid < 1280 -> Q tile (40 stages),
// bid >= 1280 -> kv tile (8 stages, backfills Q tail wave).
// ============================================================================
struct QKVArgs {
    const __half *ahi, *ehi;
    const __half *wq, *wt;
    __half *qhi;
    float* pbuf;
};

__global__ __launch_bounds__(256, 2)
void hmma_gemm_qkv(QKVArgs args)
{
    extern __shared__ __align__(16) char smx[];
    const uint32_t smb = smem_to_u32(smx);
    const int tid = threadIdx.x;
    const int bid = blockIdx.x;
    const bool isQ = bid < 1280;

    const int lr0 = tid >> 2;
    const int cch = tid & 3;

    const __half *Ahi, *Bm;
    int K, NS, kBase, colBase, rowBase = 0, part = 0, split = 0;
    int aRow[2];
    int aBytes[2];

    if (isQ) {
        rowBase = (bid / 10) * 128;
        colBase = (bid % 10) * 128;
        Ahi = args.ahi;
        Bm = args.wq;
        K = HIDDEN; NS = 40; kBase = 0;
        aRow[0] = rowBase + lr0;
        aRow[1] = rowBase + lr0 + 64;
        aBytes[0] = 16; aBytes[1] = 16;
    } else {
        const int t = bid - 1280;
        colBase = (t % 10) * 128;
        part = (t / 10) & 7;
        split = t / 80;
        const int gemm = part < 3 ? 0 : (part < 6 ? 1 : (part == 6 ? 2 : 3));
        Ahi = args.ehi;
        Bm = args.wt + (long)gemm * HIDDEN * CROSS;
        K = CROSS; NS = 8; kBase = split * 256;
        long ar, cr;
        aBytes[0] = kv_map(part, lr0, ar, cr) ? 16 : 0;      aRow[0] = (int)ar;
        aBytes[1] = kv_map(part, lr0 + 64, ar, cr) ? 16 : 0; aRow[1] = (int)ar;
    }

    const int warp = tid >> 5, lane = tid & 31;
    const int wm = warp >> 1, wn = warp & 1;
    const int m0 = wm * 32, n0 = wn * 64;

    const uint32_t aoffs = (uint32_t)((m0 + (lane & 15)) * LDS_ROW + (lane >> 4) * 16);
    const uint32_t boffs = (uint32_t)((n0 + ((lane >> 4) & 1) * 8 + (lane & 7)) * LDS_ROW
                                      + ((lane >> 3) & 1) * 16);

    float acc[2][8][4];
    #pragma unroll
    for (int mi = 0; mi < 2; mi++)
        #pragma unroll
        for (int nj = 0; nj < 8; nj++)
            #pragma unroll
            for (int t = 0; t < 4; t++) acc[mi][nj][t] = 0.f;

    auto load_stage = [&](int s) {
        const int b = s & 1;
        const int k0 = kBase + (s << 5);
        #pragma unroll
        for (int i = 0; i < 2; i++) {
            const int r = lr0 + i * 64;
            uint32_t d = smb + (uint32_t)(b * STGBUF + r * LDS_ROW + cch * 16);
            long go = (long)aRow[i] * K + k0 + cch * 8;
            cp_async16(d + OFF_A, Ahi + go, aBytes[i]);
            long gb = (long)(colBase + r) * K + k0 + cch * 8;
            cp_async16(d + OFF_B, Bm + gb, 16);
        }
        CP_COMMIT();
    };

    load_stage(0);
    for (int s = 0; s < NS; ++s) {
        if (s + 1 < NS) {
            load_stage(s + 1);
            CP_WAIT(1);
        } else {
            CP_WAIT(0);
        }
        __syncthreads();
        gemm_stage_compute(smb + (s & 1) * STGBUF, aoffs, boffs, acc);
        __syncthreads();
    }

    // Epilogue
    const int g = lane >> 2, tig = lane & 3;
    if (isQ) {
        #pragma unroll
        for (int mi = 0; mi < 2; mi++) {
            #pragma unroll
            for (int nj = 0; nj < 8; nj++) {
                const int r0 = rowBase + m0 + mi * 16 + g;
                const int col = colBase + n0 + nj * 8 + tig * 2;
                #pragma unroll
                for (int rr = 0; rr < 2; rr++) {
                    long o = (long)(r0 + rr * 8) * HIDDEN + col;
                    *(uint32_t*)(args.qhi + o) =
                        pack_half2(acc[mi][nj][rr * 2 + 0], acc[mi][nj][rr * 2 + 1]);
                }
            }
        }
    } else {
        float* pout = args.pbuf + (long)split * PART_STRIDE;
        #pragma unroll
        for (int mi = 0; mi < 2; mi++) {
            #pragma unroll
            for (int nj = 0; nj < 8; nj++) {
                const int r0 = m0 + mi * 16 + g;
                const int col = colBase + n0 + nj * 8 + tig * 2;
                long aR, cR;
                if (kv_map(part, r0, aR, cR))
                    *(float2*)(pout + cR * HIDDEN + col) =
                        make_float2(acc[mi][nj][0], acc[mi][nj][1]);
                if (kv_map(part, r0 + 8, aR, cR))
                    *(float2*)(pout + cR * HIDDEN + col) =
                        make_float2(acc[mi][nj][2], acc[mi][nj][3]);
            }
        }
    }
}

// ============================================================================
// Out-projection GEMM (pure fp16, fused bias+resid).
// ============================================================================
struct GemmArgs {
    const __half *Ahi, *Bm;
    float* C;
    int K, ldc;
    const float *bias, *resid;
};

__global__ __launch_bounds__(256, 2)
void hmma_gemm(GemmArgs args)
{
    extern __shared__ __align__(16) char smx[];
    const uint32_t smb = smem_to_u32(smx);
    const int tid = threadIdx.x;

    const __half* Ahi = args.Ahi;
    const __half* Bm = args.Bm;
    const int K = args.K, ldc = args.ldc;

    const int rowBase = blockIdx.y * 128;
    const int colBase = blockIdx.x * 128;
    const int NS = K >> 5;
    const int lr0 = tid >> 2;
    const int cch = tid & 3;

    const int warp = tid >> 5, lane = tid & 31;
    const int wm = warp >> 1, wn = warp & 1;
    const int m0 = wm * 32, n0 = wn * 64;

    const uint32_t aoffs = (uint32_t)((m0 + (lane & 15)) * LDS_ROW + (lane >> 4) * 16);
    const uint32_t boffs = (uint32_t)((n0 + ((lane >> 4) & 1) * 8 + (lane & 7)) * LDS_ROW
                                      + ((lane >> 3) & 1) * 16);

    float acc[2][8][4];
    #pragma unroll
    for (int mi = 0; mi < 2; mi++)
        #pragma unroll
        for (int nj = 0; nj < 8; nj++)
            #pragma unroll
            for (int t = 0; t < 4; t++) acc[mi][nj][t] = 0.f;

    auto load_stage = [&](int s) {
        const int b = s & 1;
        const long k0 = (long)s << 5;
        #pragma unroll
        for (int i = 0; i < 2; i++) {
            const int r = lr0 + i * 64;
            uint32_t d = smb + (uint32_t)(b * STGBUF + r * LDS_ROW + cch * 16);
            long go = (long)(rowBase + r) * K + k0 + cch * 8;
            cp_async16(d + OFF_A, Ahi + go, 16);
            long gb = (long)(colBase + r) * K + k0 + cch * 8;
            cp_async16(d + OFF_B, Bm + gb, 16);
        }
        CP_COMMIT();
    };

    load_stage(0);
    for (int s = 0; s < NS; ++s) {
        if (s + 1 < NS) {
            load_stage(s + 1);
            CP_WAIT(1);
        } else {
            CP_WAIT(0);
        }
        __syncthreads();
        gemm_stage_compute(smb + (s & 1) * STGBUF, aoffs, boffs, acc);
        __syncthreads();
    }

    // Epilogue: fp32 + bias + residual
    const int g = lane >> 2, tig = lane & 3;
    const float* bias = args.bias;
    const float* resid = args.resid;
    #pragma unroll
    for (int mi = 0; mi < 2; mi++) {
        #pragma unroll
        for (int nj = 0; nj < 8; nj++) {
            const int r0 = rowBase + m0 + mi * 16 + g;
            const int col = colBase + n0 + nj * 8 + tig * 2;
            float2 v0 = make_float2(acc[mi][nj][0], acc[mi][nj][1]);
            float2 v1 = make_float2(acc[mi][nj][2], acc[mi][nj][3]);
            const float2 bi = *(const float2*)(bias + col);
            v0.x += bi.x; v0.y += bi.y;
            v1.x += bi.x; v1.y += bi.y;
            const float2 rr0 = *(const float2*)(resid + (long)r0 * ldc + col);
            v0.x += rr0.x; v0.y += rr0.y;
            const float2 rr1 = *(const float2*)(resid + (long)(r0 + 8) * ldc + col);
            v1.x += rr1.x; v1.y += rr1.y;
            *(float2*)(args.C + (long)r0 * ldc + col)       = v0;
            *(float2*)(args.C + (long)(r0 + 8) * ldc + col) = v1;
        }
    }
}

// Sum 8 split-K partials -> kv fp16.
__global__ __launch_bounds__(256)
void reduce_split_kv(const float* __restrict__ part, __half* __restrict__ hi)
{
    const long n4 = PART_STRIDE / 4;
    long i = (long)blockIdx.x * 256 + threadIdx.x;
    if (i >= n4) return;
    const float4* p4 = (const float4*)part;
    float4 s = p4[i];
    #pragma unroll
    for (int k = 1; k < 8; k++) {
        float4 t = p4[i + (long)k * n4];
        s.x += t.x; s.y += t.y; s.z += t.z; s.w += t.w;
    }
    ((uint2*)hi)[i] = make_uint2(pack_half2(s.x, s.y), pack_half2(s.z, s.w));
}

// ============================================================================
// HMMA flash attention: CTA = 128 q-rows x 96 keys (77 text + pad + 4 ip @80).
// 8 warps, warp = 16 rows. Pure fp16. V [key][dim] + ldsm.trans.
// Writes hs as fp16.
// ============================================================================
#define AROW 144
#define KROW 144
#define OFF_Q  0
#define OFF_K  (128 * AROW)                 // 18432
#define OFF_V  (OFF_K + 96 * KROW)          // 32256
#define SMEM_ATTN (OFF_V + 96 * KROW)       // 46080

__global__ __launch_bounds__(256)
void attn_mma(const __half* __restrict__ qhi,
              const __half* __restrict__ kv,
              __half* __restrict__ ohi)
{
    extern __shared__ __align__(16) char smx[];
    const uint32_t smb = smem_to_u32(smx);
    const int tid = threadIdx.x;
    const int b = blockIdx.z, h = blockIdx.y;
    const int rowBase = blockIdx.x * 128;
    const long SLAB = (long)NB * TXT * HIDDEN;

    // Q tile: 128 rows x 64 dims
    #pragma unroll
    for (int i = 0; i < 4; i++) {
        int idx = tid + i * 256;
        int r = idx >> 3, c = idx & 7;
        long src = ((long)b * SQ + rowBase + r) * HIDDEN + h * 64 + c * 8;
        cp_async16(smb + OFF_Q + (uint32_t)(r * AROW + c * 16), qhi + src, 16);
    }
    // K tile: rows 0-76 text K, 80-83 ipK, rest zero
    #pragma unroll
    for (int i = 0; i < 3; i++) {
        int idx = tid + i * 256;
        int r = idx >> 3, c = idx & 7;
        int bytes = 0;
        long src = 0;
        if (r < TXT) {
            bytes = 16;
            src = (long)b * TXT * HIDDEN + (long)r * HIDDEN + h * 64 + c * 8;
        } else if (r >= 80 && r < 80 + NTOK) {
            bytes = 16;
            src = 2 * SLAB + (long)b * TXT * HIDDEN + (long)(r - 80) * HIDDEN + h * 64 + c * 8;
        }
        cp_async16(smb + OFF_K + (uint32_t)(r * KROW + c * 16), kv + src, bytes);
    }
    // V tile: rows 0-76 text V, 80-83 ipV, [key][dim]
    #pragma unroll
    for (int i = 0; i < 3; i++) {
        int idx = tid + i * 256;
        int r = idx >> 3, c = idx & 7;
        int bytes = 0;
        long src = 0;
        if (r < TXT) {
            bytes = 16;
            src = SLAB + (long)b * TXT * HIDDEN + (long)r * HIDDEN + h * 64 + c * 8;
        } else if (r >= 80 && r < 80 + NTOK) {
            bytes = 16;
            src = 3 * SLAB + (long)b * TXT * HIDDEN + (long)(r - 80) * HIDDEN + h * 64 + c * 8;
        }
        cp_async16(smb + OFF_V + (uint32_t)(r * KROW + c * 16), kv + src, bytes);
    }
    CP_COMMIT();
    CP_WAIT(0);
    __syncthreads();

    const int warp = tid >> 5, lane = tid & 31;
    const int m0 = warp * 16;
    const int tig = lane & 3;
    const uint32_t aoffs = smb + OFF_Q + (uint32_t)((m0 + (lane & 15)) * AROW + (lane >> 4) * 16);
    const uint32_t kbase = smb + OFF_K
        + (uint32_t)((((lane >> 4) & 1) * 8 + (lane & 7)) * KROW + ((lane >> 3) & 1) * 16);

    // S = Q K^T (12 n-tiles of 8 keys = 96)
    float s[12][4];
    #pragma unroll
    for (int j = 0; j < 12; j++)
        #pragma unroll
        for (int e = 0; e < 4; e++) s[j][e] = 0.f;

    #pragma unroll
    for (int ks = 0; ks < 4; ks++) {
        uint32_t Qh[4];
        ldsm_x4(Qh, aoffs + ks * 32);
        #pragma unroll
        for (int t = 0; t < 6; t++) {
            uint32_t Bh[4];
            ldsm_x4(Bh, kbase + t * 16 * KROW + ks * 32);
            mma16816(s[2 * t + 0], Qh, Bh[0], Bh[1]);
            mma16816(s[2 * t + 1], Qh, Bh[2], Bh[3]);
        }
    }

    // scale + mask + dual softmax
    const bool ipOn = (b & 1);
    float mx[2]  = {-1e30f, -1e30f};
    float mx2[2] = {-1e30f, -1e30f};
    #pragma unroll
    for (int j = 0; j < 10; j++)
        #pragma unroll
        for (int e = 0; e < 4; e++) {
            int col = j * 8 + tig * 2 + (e & 1);
            float v = s[j][e] * 0.125f;
            s[j][e] = (col < TXT) ? v : -1e30f;
            mx[e >> 1] = fmaxf(mx[e >> 1], s[j][e]);
        }
    #pragma unroll
    for (int j = 10; j < 12; j++)
        #pragma unroll
        for (int e = 0; e < 4; e++) {
            int col = j * 8 + tig * 2 + (e & 1);
            float v = s[j][e] * 0.125f;
            s[j][e] = (col >= 80 && col < 80 + NTOK) ? v : -1e30f;
            mx2[e >> 1] = fmaxf(mx2[e >> 1], s[j][e]);
        }
    #pragma unroll
    for (int off = 1; off <= 2; off <<= 1) {
        mx[0]  = fmaxf(mx[0],  __shfl_xor_sync(0xffffffffu, mx[0],  off));
        mx[1]  = fmaxf(mx[1],  __shfl_xor_sync(0xffffffffu, mx[1],  off));
        mx2[0] = fmaxf(mx2[0], __shfl_xor_sync(0xffffffffu, mx2[0], off));
        mx2[1] = fmaxf(mx2[1], __shfl_xor_sync(0xffffffffu, mx2[1], off));
    }
    float l[2] = {0.f, 0.f}, l2[2] = {0.f, 0.f};
    #pragma unroll
    for (int j = 0; j < 10; j++)
        #pragma unroll
        for (int e = 0; e < 4; e++) {
            float p = __expf(s[j][e] - mx[e >> 1]);
            s[j][e] = p;
            l[e >> 1] += p;
        }
    #pragma unroll
    for (int j = 10; j < 12; j++)
        #pragma unroll
        for (int e = 0; e < 4; e++) {
            float p = __expf(s[j][e] - mx2[e >> 1]);
            s[j][e] = p;
            l2[e >> 1] += p;
        }
    #pragma unroll
    for (int off = 1; off <= 2; off <<= 1) {
        l[0]  += __shfl_xor_sync(0xffffffffu, l[0],  off);
        l[1]  += __shfl_xor_sync(0xffffffffu, l[1],  off);
        l2[0] += __shfl_xor_sync(0xffffffffu, l2[0], off);
        l2[1] += __shfl_xor_sync(0xffffffffu, l2[1], off);
    }
    float inv[2], inv2[2];
    inv[0] = 1.f / l[0];
    inv[1] = 1.f / l[1];
    inv2[0] = ipOn ? 1.f / l2[0] : 0.f;
    inv2[1] = ipOn ? 1.f / l2[1] : 0.f;
    #pragma unroll
    for (int j = 0; j < 10; j++)
        #pragma unroll
        for (int e = 0; e < 4; e++) s[j][e] *= inv[e >> 1];
    #pragma unroll
    for (int j = 10; j < 12; j++)
        #pragma unroll
        for (int e = 0; e < 4; e++) s[j][e] *= inv2[e >> 1];

    // PV via ldsm.trans on V[key][dim]
    const uint32_t vtbase = smb + OFF_V
        + (uint32_t)((((lane >> 3) & 1) * 8 + (lane & 7)) * KROW + ((lane >> 4) & 1) * 16);
    float out[8][4];
    #pragma unroll
    for (int d = 0; d < 8; d++)
        #pragma unroll
        for (int e = 0; e < 4; e++) out[d][e] = 0.f;

    #pragma unroll
    for (int kk = 0; kk < 6; kk++) {
        uint32_t ah[4];
        #pragma unroll
        for (int r = 0; r < 4; r++) {
            const int t = 2 * kk + (r >> 1);
            const int pi = (r & 1) * 2;
            ah[r] = pack_half2(s[t][pi], s[t][pi + 1]);
        }
        #pragma unroll
        for (int d = 0; d < 4; d++) {
            uint32_t Vh[4];
            ldsm_x4_t(Vh, vtbase + kk * 16 * KROW + d * 32);
            mma16816(out[2 * d + 0], ah, Vh[0], Vh[1]);
            mma16816(out[2 * d + 1], ah, Vh[2], Vh[3]);
        }
    }

    // write hs fp16
    const int g = lane >> 2;
    const long row0 = (long)b * SQ + rowBase + m0 + g;
    #pragma unroll
    for (int d = 0; d < 8; d++) {
        const int col = h * 64 + d * 8 + tig * 2;
        #pragma unroll
        for (int rr = 0; rr < 2; rr++) {
            long o = (row0 + rr * 8) * HIDDEN + col;
            *(uint32_t*)(ohi + o) = pack_half2(out[d][rr * 2 + 0], out[d][rr * 2 + 1]);
        }
    }
}

// ============================================================================
// Launcher
// ============================================================================
extern "C" void kernel_launch(void* const* d_in, const int* in_sizes, int n_in,
                              void* d_out, int out_size)
{
    const float* hidden = (const float*)d_in[0];
    const float* enc    = (const float*)d_in[1];
    const float* Wq     = (const float*)d_in[2];
    const float* Wk     = (const float*)d_in[3];
    const float* Wv     = (const float*)d_in[4];
    const float* Wk_ip  = (const float*)d_in[5];
    const float* Wv_ip  = (const float*)d_in[6];
    const float* Wout   = (const float*)d_in[7];
    const float* b_out  = (const float*)d_in[8];
    float* out = (float*)d_out;

    static bool attr_set = false;
    if (!attr_set) {
        cudaFuncSetAttribute(hmma_gemm, cudaFuncAttributeMaxDynamicSharedMemorySize, SMEM_TOT);
        cudaFuncSetAttribute(hmma_gemm_qkv, cudaFuncAttributeMaxDynamicSharedMemorySize, SMEM_TOT);
        cudaFuncSetAttribute(attn_mma, cudaFuncAttributeMaxDynamicSharedMemorySize, SMEM_ATTN);
        attr_set = true;
    }

    __half *ahi, *qhi, *ehi, *wq, *wt, *wo, *kv;
    float* pbuf;
    cudaGetSymbolAddress((void**)&ahi, g_ahi);
    cudaGetSymbolAddress((void**)&qhi, g_qhi);
    cudaGetSymbolAddress((void**)&ehi, g_ehi);
    cudaGetSymbolAddress((void**)&wq,  g_wqT);
    cudaGetSymbolAddress((void**)&wt,  g_wT);
    cudaGetSymbolAddress((void**)&wo,  g_woutT);
    cudaGetSymbolAddress((void**)&kv,  g_kv);
    cudaGetSymbolAddress((void**)&pbuf, g_part);

    const int M_big = NB * SQ;  // 16384
    const long WSLAB = (long)HIDDEN * CROSS;

    // 1) activation fp16 converts
    {
        int n4 = M_big * HIDDEN / 4;
        split_hi_kernel<<<(n4 + 255) / 256, 256>>>(hidden, ahi, n4);
    }
    {
        int n4 = NB * ENC * CROSS / 4;
        split_hi_kernel<<<(n4 + 255) / 256, 256>>>(enc, ehi, n4);
    }

    // 2) all weight transposes in one launch
    {
        TSArgs t;
        t.src[0] = Wq;    t.dst[0] = wq;             t.K[0] = HIDDEN;
        t.src[1] = Wk;    t.dst[1] = wt + 0 * WSLAB; t.K[1] = CROSS;
        t.src[2] = Wv;    t.dst[2] = wt + 1 * WSLAB; t.K[2] = CROSS;
        t.src[3] = Wk_ip; t.dst[3] = wt + 2 * WSLAB; t.K[3] = CROSS;
        t.src[4] = Wv_ip; t.dst[4] = wt + 3 * WSLAB; t.K[4] = CROSS;
        t.src[5] = Wout;  t.dst[5] = wo;             t.K[5] = HIDDEN;
        transpose_all<<<dim3(HIDDEN / 32, CROSS / 32, 6), dim3(32, 8)>>>(t);
    }

    // 3) merged Q projection + packed split-K kv projections (1920 CTAs)
    {
        QKVArgs a;
        a.ahi = ahi; a.ehi = ehi;
        a.wq = wq; a.wt = wt;
        a.qhi = qhi; a.pbuf = pbuf;
        hmma_gemm_qkv<<<1920, 256, SMEM_TOT>>>(a);
    }

    // 4) reduce split-K partials -> kv fp16
    {
        long n4 = PART_STRIDE / 4;
        reduce_split_kv<<<(int)((n4 + 255) / 256), 256>>>(pbuf, kv);
    }

    // 5) HMMA attention -> hs fp16 (reuses g_ahi)
    attn_mma<<<dim3(SQ / 128, NHEADS, NB), 256, SMEM_ATTN>>>(qhi, kv, ahi);

    // 6) out = hs @ Wout + b_out + residual (fp32)
    {
        GemmArgs a = {ahi, wo, out, HIDDEN, HIDDEN, b_out, hidden};
        hmma_gemm<<<dim3(HIDDEN / 128, M_big / 128, 1), 256, SMEM_TOT>>>(a);
    }
}

// round 12
// speedup vs baseline: 2.3142x; 1.1432x over previous
#include <cuda_runtime.h>
#include <cuda_fp16.h>
#include <cstdint>

#define NHEADS 20
#define HEAD_DIM 64
#define HIDDEN 1280
#define CROSS 2048
#define NB 4
#define SQ 4096
#define TXT 77
#define NTOK 4
#define ENC (TXT + NTOK)

// ============================================================================
// PTX helpers (baseline-family only: mma.sync / ldmatrix / cp.async)
// ============================================================================
__device__ __forceinline__ uint32_t smem_to_u32(const void* smem_ptr) {
    uint32_t addr;
    asm("{ .reg .u64 tmp; cvta.to.shared.u64 tmp, %1; cvt.u32.u64 %0, tmp; }"
        : "=r"(addr) : "l"(smem_ptr));
    return addr;
}

__device__ __forceinline__ void cp_async16(uint32_t dst, const void* src, int bytes) {
    asm volatile("cp.async.cg.shared.global [%0], [%1], 16, %2;"
                 :: "r"(dst), "l"(src), "r"(bytes));
}
#define CP_COMMIT() asm volatile("cp.async.commit_group;" ::: "memory")
#define CP_WAIT(N)  asm volatile("cp.async.wait_group %0;" :: "n"(N) : "memory")

__device__ __forceinline__ void ldsm_x4(uint32_t* r, uint32_t a) {
    asm volatile("ldmatrix.sync.aligned.m8n8.x4.shared.b16 {%0,%1,%2,%3}, [%4];"
                 : "=r"(r[0]), "=r"(r[1]), "=r"(r[2]), "=r"(r[3]) : "r"(a));
}

__device__ __forceinline__ void ldsm_x4_t(uint32_t* r, uint32_t a) {
    asm volatile("ldmatrix.sync.aligned.m8n8.x4.trans.shared.b16 {%0,%1,%2,%3}, [%4];"
                 : "=r"(r[0]), "=r"(r[1]), "=r"(r[2]), "=r"(r[3]) : "r"(a));
}

// f16 x f16 -> f32 MMA
__device__ __forceinline__ void mma16816(float* c, const uint32_t* a,
                                         uint32_t b0, uint32_t b1) {
    asm volatile(
        "mma.sync.aligned.m16n8k16.row.col.f32.f16.f16.f32 "
        "{%0,%1,%2,%3},{%4,%5,%6,%7},{%8,%9},{%0,%1,%2,%3};"
        : "+f"(c[0]), "+f"(c[1]), "+f"(c[2]), "+f"(c[3])
        : "r"(a[0]), "r"(a[1]), "r"(a[2]), "r"(a[3]), "r"(b0), "r"(b1));
}

__device__ __forceinline__ uint32_t pack_half2(float a, float b) {
    __half2 t;
    t.x = __float2half(a);
    t.y = __float2half(b);
    return *reinterpret_cast<uint32_t*>(&t);
}

// ============================================================================
// Scratch (static device allocations)
// ============================================================================
#define PART_STRIDE ((long)16 * TXT * HIDDEN)   // floats per split-K partial

__device__ __half g_ahi[NB * SQ * HIDDEN];            // hidden-hi, then hs-hi
__device__ __half g_qhi[NB * SQ * HIDDEN];
__device__ __half g_ehi[NB * ENC * CROSS];
__device__ __half g_wqT[HIDDEN * HIDDEN];
__device__ __half g_wT[4 * HIDDEN * CROSS];           // wk, wv, wkip, wvip (T)
__device__ __half g_woutT[HIDDEN * HIDDEN];
__device__ __half g_kv[4 * NB * TXT * HIDDEN];        // k,v,ipk,ipv
__device__ float g_part[8 * 16 * TXT * HIDDEN];       // split-K partials

// ============================================================================
// fp32 -> fp16 convert (activations)
// ============================================================================
__global__ __launch_bounds__(256)
void split_hi_kernel(const float* __restrict__ in, __half* __restrict__ hi, int n4)
{
    int i = blockIdx.x * blockDim.x + threadIdx.x;
    if (i >= n4) return;
    float4 x = ((const float4*)in)[i];
    ((uint2*)hi)[i] = make_uint2(pack_half2(x.x, x.y), pack_half2(x.z, x.w));
}

// ============================================================================
// Merged transpose + fp16 convert of all 6 weights (grid.z selects weight).
// ============================================================================
struct TSArgs {
    const float* src[6];
    __half* dst[6];
    int K[6];
};

__global__ __launch_bounds__(256)
void transpose_all(TSArgs args)
{
    const int w = blockIdx.z;
    const int K = args.K[w];
    const int k0 = blockIdx.y * 32;
    if (k0 >= K) return;
    const float* in = args.src[w];
    __half* dst = args.dst[w];

    __shared__ float t[32][33];
    const int tx = threadIdx.x, ty = threadIdx.y;
    const int n0 = blockIdx.x * 32;
    #pragma unroll
    for (int j = ty; j < 32; j += 8)
        t[j][tx] = in[(long)(k0 + j) * HIDDEN + n0 + tx];
    __syncthreads();
    #pragma unroll
    for (int j = ty; j < 32; j += 8)
        dst[(long)(n0 + j) * K + k0 + tx] = __float2half(t[tx][j]);
}

// ============================================================================
// Shared GEMM pieces: CTA 128x128x64 (BK=64), 8 warps, warp 32x64, cp.async
// double buffer, pure fp16. 144B rows (128B data + 16B pad, conflict-free).
// ============================================================================
#define LDS_ROW 144
#define TILE_B  18432            // 128 rows * 144B
#define OFF_A   0
#define OFF_B   18432
#define STGBUF  36864            // A + B per stage
#define SMEM_TOT 73728           // 2 stages

// Interleaved per-accumulator compute (do NOT burst-reorder; see R8).
__device__ __forceinline__ void gemm_stage_compute(
    uint32_t base, uint32_t aoffs, uint32_t boffs, float acc[2][8][4])
{
    const uint32_t aA = base + OFF_A;
    const uint32_t bB = base + OFF_B;
    #pragma unroll
    for (int ks = 0; ks < 4; ks++) {
        uint32_t Ah[2][4];
        #pragma unroll
        for (int mi = 0; mi < 2; mi++)
            ldsm_x4(Ah[mi], aA + aoffs + mi * 16 * LDS_ROW + ks * 32);
        #pragma unroll
        for (int half = 0; half < 2; half++) {
            uint32_t Bh[2][4];
            #pragma unroll
            for (int nn = 0; nn < 2; nn++)
                ldsm_x4(Bh[nn], bB + boffs + (half * 2 + nn) * 16 * LDS_ROW + ks * 32);
            #pragma unroll
            for (int mi = 0; mi < 2; mi++) {
                #pragma unroll
                for (int j4 = 0; j4 < 4; j4++) {
                    const int ni = j4 >> 1, h = (j4 & 1) * 2;
                    mma16816(acc[mi][half * 4 + j4], Ah[mi], Bh[ni][h], Bh[ni][h + 1]);
                }
            }
        }
    }
}

// kv packed-row map: parts 0-2 text K (4x77 rows), 3-5 text V, 6 ipK (16), 7 ipV.
__device__ __forceinline__ bool kv_map(int part, int r, long& aRow, long& cRow)
{
    aRow = 0; cRow = 0;
    if (part < 6) {
        int R = (part % 3) * 128 + r;
        if (R >= 4 * TXT) return false;
        int batch = R / TXT, rr = R - batch * TXT;
        aRow = (long)batch * ENC + rr;
        cRow = (long)(((part < 3 ? 0 : 1) * 4 + batch) * TXT + rr);
        return true;
    } else {
        if (r >= 16) return false;
        int batch = r >> 2, rr = r & 3;
        aRow = (long)batch * ENC + TXT + rr;
        cRow = (long)(((part == 6 ? 2 : 3) * 4 + batch) * TXT + rr);
        return true;
    }
}

// ============================================================================
// Merged Q-projection + packed split-K kv-projection GEMM (BK=64).
// 1-D grid of 1920 CTAs: bid < 1280 -> Q tile (20 stages),
// bid >= 1280 -> kv tile (4 stages, backfills Q tail wave).
// ============================================================================
struct QKVArgs {
    const __half *ahi, *ehi;
    const __half *wq, *wt;
    __half *qhi;
    float* pbuf;
};

__global__ __launch_bounds__(256, 2)
void hmma_gemm_qkv(QKVArgs args)
{
    extern __shared__ __align__(16) char smx[];
    const uint32_t smb = smem_to_u32(smx);
    const int tid = threadIdx.x;
    const int bid = blockIdx.x;
    const bool isQ = bid < 1280;

    // loader mapping: row lr+{0,32,64,96}, col chunk cch (8 x 16B per 128B row)
    const int lr  = tid >> 3;
    const int cch = tid & 7;

    const __half *Ahi, *Bm;
    int K, NS, kBase, colBase, rowBase = 0, part = 0, split = 0;
    int aRow[4];
    int aBytes[4];

    if (isQ) {
        rowBase = (bid / 10) * 128;
        colBase = (bid % 10) * 128;
        Ahi = args.ahi;
        Bm = args.wq;
        K = HIDDEN; NS = 20; kBase = 0;
        #pragma unroll
        for (int i = 0; i < 4; i++) {
            aRow[i] = rowBase + lr + i * 32;
            aBytes[i] = 16;
        }
    } else {
        const int t = bid - 1280;
        colBase = (t % 10) * 128;
        part = (t / 10) & 7;
        split = t / 80;
        const int gemm = part < 3 ? 0 : (part < 6 ? 1 : (part == 6 ? 2 : 3));
        Ahi = args.ehi;
        Bm = args.wt + (long)gemm * HIDDEN * CROSS;
        K = CROSS; NS = 4; kBase = split * 256;
        #pragma unroll
        for (int i = 0; i < 4; i++) {
            long ar, cr;
            aBytes[i] = kv_map(part, lr + i * 32, ar, cr) ? 16 : 0;
            aRow[i] = (int)ar;
        }
    }

    const int warp = tid >> 5, lane = tid & 31;
    const int wm = warp >> 1, wn = warp & 1;
    const int m0 = wm * 32, n0 = wn * 64;

    const uint32_t aoffs = (uint32_t)((m0 + (lane & 15)) * LDS_ROW + (lane >> 4) * 16);
    const uint32_t boffs = (uint32_t)((n0 + ((lane >> 4) & 1) * 8 + (lane & 7)) * LDS_ROW
                                      + ((lane >> 3) & 1) * 16);

    float acc[2][8][4];
    #pragma unroll
    for (int mi = 0; mi < 2; mi++)
        #pragma unroll
        for (int nj = 0; nj < 8; nj++)
            #pragma unroll
            for (int t = 0; t < 4; t++) acc[mi][nj][t] = 0.f;

    auto load_stage = [&](int s) {
        const int b = s & 1;
        const int k0 = kBase + (s << 6);
        #pragma unroll
        for (int i = 0; i < 4; i++) {
            const int r = lr + i * 32;
            uint32_t d = smb + (uint32_t)(b * STGBUF + r * LDS_ROW + cch * 16);
            long go = (long)aRow[i] * K + k0 + cch * 8;
            cp_async16(d + OFF_A, Ahi + go, aBytes[i]);
            long gb = (long)(colBase + r) * K + k0 + cch * 8;
            cp_async16(d + OFF_B, Bm + gb, 16);
        }
        CP_COMMIT();
    };

    load_stage(0);
    for (int s = 0; s < NS; ++s) {
        if (s + 1 < NS) {
            load_stage(s + 1);
            CP_WAIT(1);
        } else {
            CP_WAIT(0);
        }
        __syncthreads();
        gemm_stage_compute(smb + (s & 1) * STGBUF, aoffs, boffs, acc);
        __syncthreads();
    }

    // Epilogue
    const int g = lane >> 2, tig = lane & 3;
    if (isQ) {
        #pragma unroll
        for (int mi = 0; mi < 2; mi++) {
            #pragma unroll
            for (int nj = 0; nj < 8; nj++) {
                const int r0 = rowBase + m0 + mi * 16 + g;
                const int col = colBase + n0 + nj * 8 + tig * 2;
                #pragma unroll
                for (int rr = 0; rr < 2; rr++) {
                    long o = (long)(r0 + rr * 8) * HIDDEN + col;
                    *(uint32_t*)(args.qhi + o) =
                        pack_half2(acc[mi][nj][rr * 2 + 0], acc[mi][nj][rr * 2 + 1]);
                }
            }
        }
    } else {
        float* pout = args.pbuf + (long)split * PART_STRIDE;
        #pragma unroll
        for (int mi = 0; mi < 2; mi++) {
            #pragma unroll
            for (int nj = 0; nj < 8; nj++) {
                const int r0 = m0 + mi * 16 + g;
                const int col = colBase + n0 + nj * 8 + tig * 2;
                long aR, cR;
                if (kv_map(part, r0, aR, cR))
                    *(float2*)(pout + cR * HIDDEN + col) =
                        make_float2(acc[mi][nj][0], acc[mi][nj][1]);
                if (kv_map(part, r0 + 8, aR, cR))
                    *(float2*)(pout + cR * HIDDEN + col) =
                        make_float2(acc[mi][nj][2], acc[mi][nj][3]);
            }
        }
    }
}

// ============================================================================
// Out-projection GEMM (BK=64, pure fp16, fused bias+resid).
// ============================================================================
struct GemmArgs {
    const __half *Ahi, *Bm;
    float* C;
    int K, ldc;
    const float *bias, *resid;
};

__global__ __launch_bounds__(256, 2)
void hmma_gemm(GemmArgs args)
{
    extern __shared__ __align__(16) char smx[];
    const uint32_t smb = smem_to_u32(smx);
    const int tid = threadIdx.x;

    const __half* Ahi = args.Ahi;
    const __half* Bm = args.Bm;
    const int K = args.K, ldc = args.ldc;

    const int rowBase = blockIdx.y * 128;
    const int colBase = blockIdx.x * 128;
    const int NS = K >> 6;
    const int lr  = tid >> 3;
    const int cch = tid & 7;

    const int warp = tid >> 5, lane = tid & 31;
    const int wm = warp >> 1, wn = warp & 1;
    const int m0 = wm * 32, n0 = wn * 64;

    const uint32_t aoffs = (uint32_t)((m0 + (lane & 15)) * LDS_ROW + (lane >> 4) * 16);
    const uint32_t boffs = (uint32_t)((n0 + ((lane >> 4) & 1) * 8 + (lane & 7)) * LDS_ROW
                                      + ((lane >> 3) & 1) * 16);

    float acc[2][8][4];
    #pragma unroll
    for (int mi = 0; mi < 2; mi++)
        #pragma unroll
        for (int nj = 0; nj < 8; nj++)
            #pragma unroll
            for (int t = 0; t < 4; t++) acc[mi][nj][t] = 0.f;

    auto load_stage = [&](int s) {
        const int b = s & 1;
        const long k0 = (long)s << 6;
        #pragma unroll
        for (int i = 0; i < 4; i++) {
            const int r = lr + i * 32;
            uint32_t d = smb + (uint32_t)(b * STGBUF + r * LDS_ROW + cch * 16);
            long go = (long)(rowBase + r) * K + k0 + cch * 8;
            cp_async16(d + OFF_A, Ahi + go, 16);
            long gb = (long)(colBase + r) * K + k0 + cch * 8;
            cp_async16(d + OFF_B, Bm + gb, 16);
        }
        CP_COMMIT();
    };

    load_stage(0);
    for (int s = 0; s < NS; ++s) {
        if (s + 1 < NS) {
            load_stage(s + 1);
            CP_WAIT(1);
        } else {
            CP_WAIT(0);
        }
        __syncthreads();
        gemm_stage_compute(smb + (s & 1) * STGBUF, aoffs, boffs, acc);
        __syncthreads();
    }

    // Epilogue: fp32 + bias + residual
    const int g = lane >> 2, tig = lane & 3;
    const float* bias = args.bias;
    const float* resid = args.resid;
    #pragma unroll
    for (int mi = 0; mi < 2; mi++) {
        #pragma unroll
        for (int nj = 0; nj < 8; nj++) {
            const int r0 = rowBase + m0 + mi * 16 + g;
            const int col = colBase + n0 + nj * 8 + tig * 2;
            float2 v0 = make_float2(acc[mi][nj][0], acc[mi][nj][1]);
            float2 v1 = make_float2(acc[mi][nj][2], acc[mi][nj][3]);
            const float2 bi = *(const float2*)(bias + col);
            v0.x += bi.x; v0.y += bi.y;
            v1.x += bi.x; v1.y += bi.y;
            const float2 rr0 = *(const float2*)(resid + (long)r0 * ldc + col);
            v0.x += rr0.x; v0.y += rr0.y;
            const float2 rr1 = *(const float2*)(resid + (long)(r0 + 8) * ldc + col);
            v1.x += rr1.x; v1.y += rr1.y;
            *(float2*)(args.C + (long)r0 * ldc + col)       = v0;
            *(float2*)(args.C + (long)(r0 + 8) * ldc + col) = v1;
        }
    }
}

// Sum 8 split-K partials -> kv fp16.
__global__ __launch_bounds__(256)
void reduce_split_kv(const float* __restrict__ part, __half* __restrict__ hi)
{
    const long n4 = PART_STRIDE / 4;
    long i = (long)blockIdx.x * 256 + threadIdx.x;
    if (i >= n4) return;
    const float4* p4 = (const float4*)part;
    float4 s = p4[i];
    #pragma unroll
    for (int k = 1; k < 8; k++) {
        float4 t = p4[i + (long)k * n4];
        s.x += t.x; s.y += t.y; s.z += t.z; s.w += t.w;
    }
    ((uint2*)hi)[i] = make_uint2(pack_half2(s.x, s.y), pack_half2(s.z, s.w));
}

// ============================================================================
// HMMA flash attention: CTA = 128 q-rows x 96 keys (77 text + pad + 4 ip @80).
// 8 warps, warp = 16 rows. Pure fp16. V [key][dim] + ldsm.trans.
// Writes hs as fp16.
// ============================================================================
#define AROW 144
#define KROW 144
#define OFF_Q  0
#define OFF_K  (128 * AROW)                 // 18432
#define OFF_V  (OFF_K + 96 * KROW)          // 32256
#define SMEM_ATTN (OFF_V + 96 * KROW)       // 46080

__global__ __launch_bounds__(256)
void attn_mma(const __half* __restrict__ qhi,
              const __half* __restrict__ kv,
              __half* __restrict__ ohi)
{
    extern __shared__ __align__(16) char smx[];
    const uint32_t smb = smem_to_u32(smx);
    const int tid = threadIdx.x;
    const int b = blockIdx.z, h = blockIdx.y;
    const int rowBase = blockIdx.x * 128;
    const long SLAB = (long)NB * TXT * HIDDEN;

    // Q tile: 128 rows x 64 dims
    #pragma unroll
    for (int i = 0; i < 4; i++) {
        int idx = tid + i * 256;
        int r = idx >> 3, c = idx & 7;
        long src = ((long)b * SQ + rowBase + r) * HIDDEN + h * 64 + c * 8;
        cp_async16(smb + OFF_Q + (uint32_t)(r * AROW + c * 16), qhi + src, 16);
    }
    // K tile: rows 0-76 text K, 80-83 ipK, rest zero
    #pragma unroll
    for (int i = 0; i < 3; i++) {
        int idx = tid + i * 256;
        int r = idx >> 3, c = idx & 7;
        int bytes = 0;
        long src = 0;
        if (r < TXT) {
            bytes = 16;
            src = (long)b * TXT * HIDDEN + (long)r * HIDDEN + h * 64 + c * 8;
        } else if (r >= 80 && r < 80 + NTOK) {
            bytes = 16;
            src = 2 * SLAB + (long)b * TXT * HIDDEN + (long)(r - 80) * HIDDEN + h * 64 + c * 8;
        }
        cp_async16(smb + OFF_K + (uint32_t)(r * KROW + c * 16), kv + src, bytes);
    }
    // V tile: rows 0-76 text V, 80-83 ipV, [key][dim]
    #pragma unroll
    for (int i = 0; i < 3; i++) {
        int idx = tid + i * 256;
        int r = idx >> 3, c = idx & 7;
        int bytes = 0;
        long src = 0;
        if (r < TXT) {
            bytes = 16;
            src = SLAB + (long)b * TXT * HIDDEN + (long)r * HIDDEN + h * 64 + c * 8;
        } else if (r >= 80 && r < 80 + NTOK) {
            bytes = 16;
            src = 3 * SLAB + (long)b * TXT * HIDDEN + (long)(r - 80) * HIDDEN + h * 64 + c * 8;
        }
        cp_async16(smb + OFF_V + (uint32_t)(r * KROW + c * 16), kv + src, bytes);
    }
    CP_COMMIT();
    CP_WAIT(0);
    __syncthreads();

    const int warp = tid >> 5, lane = tid & 31;
    const int m0 = warp * 16;
    const int tig = lane & 3;
    const uint32_t aoffs = smb + OFF_Q + (uint32_t)((m0 + (lane & 15)) * AROW + (lane >> 4) * 16);
    const uint32_t kbase = smb + OFF_K
        + (uint32_t)((((lane >> 4) & 1) * 8 + (lane & 7)) * KROW + ((lane >> 3) & 1) * 16);

    // S = Q K^T (12 n-tiles of 8 keys = 96)
    float s[12][4];
    #pragma unroll
    for (int j = 0; j < 12; j++)
        #pragma unroll
        for (int e = 0; e < 4; e++) s[j][e] = 0.f;

    #pragma unroll
    for (int ks = 0; ks < 4; ks++) {
        uint32_t Qh[4];
        ldsm_x4(Qh, aoffs + ks * 32);
        #pragma unroll
        for (int t = 0; t < 6; t++) {
            uint32_t Bh[4];
            ldsm_x4(Bh, kbase + t * 16 * KROW + ks * 32);
            mma16816(s[2 * t + 0], Qh, Bh[0], Bh[1]);
            mma16816(s[2 * t + 1], Qh, Bh[2], Bh[3]);
        }
    }

    // scale + mask + dual softmax
    const bool ipOn = (b & 1);
    float mx[2]  = {-1e30f, -1e30f};
    float mx2[2] = {-1e30f, -1e30f};
    #pragma unroll
    for (int j = 0; j < 10; j++)
        #pragma unroll
        for (int e = 0; e < 4; e++) {
            int col = j * 8 + tig * 2 + (e & 1);
            float v = s[j][e] * 0.125f;
            s[j][e] = (col < TXT) ? v : -1e30f;
            mx[e >> 1] = fmaxf(mx[e >> 1], s[j][e]);
        }
    #pragma unroll
    for (int j = 10; j < 12; j++)
        #pragma unroll
        for (int e = 0; e < 4; e++) {
            int col = j * 8 + tig * 2 + (e & 1);
            float v = s[j][e] * 0.125f;
            s[j][e] = (col >= 80 && col < 80 + NTOK) ? v : -1e30f;
            mx2[e >> 1] = fmaxf(mx2[e >> 1], s[j][e]);
        }
    #pragma unroll
    for (int off = 1; off <= 2; off <<= 1) {
        mx[0]  = fmaxf(mx[0],  __shfl_xor_sync(0xffffffffu, mx[0],  off));
        mx[1]  = fmaxf(mx[1],  __shfl_xor_sync(0xffffffffu, mx[1],  off));
        mx2[0] = fmaxf(mx2[0], __shfl_xor_sync(0xffffffffu, mx2[0], off));
        mx2[1] = fmaxf(mx2[1], __shfl_xor_sync(0xffffffffu, mx2[1], off));
    }
    float l[2] = {0.f, 0.f}, l2[2] = {0.f, 0.f};
    #pragma unroll
    for (int j = 0; j < 10; j++)
        #pragma unroll
        for (int e = 0; e < 4; e++) {
            float p = __expf(s[j][e] - mx[e >> 1]);
            s[j][e] = p;
            l[e >> 1] += p;
        }
    #pragma unroll
    for (int j = 10; j < 12; j++)
        #pragma unroll
        for (int e = 0; e < 4; e++) {
            float p = __expf(s[j][e] - mx2[e >> 1]);
            s[j][e] = p;
            l2[e >> 1] += p;
        }
    #pragma unroll
    for (int off = 1; off <= 2; off <<= 1) {
        l[0]  += __shfl_xor_sync(0xffffffffu, l[0],  off);
        l[1]  += __shfl_xor_sync(0xffffffffu, l[1],  off);
        l2[0] += __shfl_xor_sync(0xffffffffu, l2[0], off);
        l2[1] += __shfl_xor_sync(0xffffffffu, l2[1], off);
    }
    float inv[2], inv2[2];
    inv[0] = 1.f / l[0];
    inv[1] = 1.f / l[1];
    inv2[0] = ipOn ? 1.f / l2[0] : 0.f;
    inv2[1] = ipOn ? 1.f / l2[1] : 0.f;
    #pragma unroll
    for (int j = 0; j < 10; j++)
        #pragma unroll
        for (int e = 0; e < 4; e++) s[j][e] *= inv[e >> 1];
    #pragma unroll
    for (int j = 10; j < 12; j++)
        #pragma unroll
        for (int e = 0; e < 4; e++) s[j][e] *= inv2[e >> 1];

    // PV via ldsm.trans on V[key][dim]
    const uint32_t vtbase = smb + OFF_V
        + (uint32_t)((((lane >> 3) & 1) * 8 + (lane & 7)) * KROW + ((lane >> 4) & 1) * 16);
    float out[8][4];
    #pragma unroll
    for (int d = 0; d < 8; d++)
        #pragma unroll
        for (int e = 0; e < 4; e++) out[d][e] = 0.f;

    #pragma unroll
    for (int kk = 0; kk < 6; kk++) {
        uint32_t ah[4];
        #pragma unroll
        for (int r = 0; r < 4; r++) {
            const int t = 2 * kk + (r >> 1);
            const int pi = (r & 1) * 2;
            ah[r] = pack_half2(s[t][pi], s[t][pi + 1]);
        }
        #pragma unroll
        for (int d = 0; d < 4; d++) {
            uint32_t Vh[4];
            ldsm_x4_t(Vh, vtbase + kk * 16 * KROW + d * 32);
            mma16816(out[2 * d + 0], ah, Vh[0], Vh[1]);
            mma16816(out[2 * d + 1], ah, Vh[2], Vh[3]);
        }
    }

    // write hs fp16
    const int g = lane >> 2;
    const long row0 = (long)b * SQ + rowBase + m0 + g;
    #pragma unroll
    for (int d = 0; d < 8; d++) {
        const int col = h * 64 + d * 8 + tig * 2;
        #pragma unroll
        for (int rr = 0; rr < 2; rr++) {
            long o = (row0 + rr * 8) * HIDDEN + col;
            *(uint32_t*)(ohi + o) = pack_half2(out[d][rr * 2 + 0], out[d][rr * 2 + 1]);
        }
    }
}

// ============================================================================
// Launcher
// ============================================================================
extern "C" void kernel_launch(void* const* d_in, const int* in_sizes, int n_in,
                              void* d_out, int out_size)
{
    const float* hidden = (const float*)d_in[0];
    const float* enc    = (const float*)d_in[1];
    const float* Wq     = (const float*)d_in[2];
    const float* Wk     = (const float*)d_in[3];
    const float* Wv     = (const float*)d_in[4];
    const float* Wk_ip  = (const float*)d_in[5];
    const float* Wv_ip  = (const float*)d_in[6];
    const float* Wout   = (const float*)d_in[7];
    const float* b_out  = (const float*)d_in[8];
    float* out = (float*)d_out;

    static bool attr_set = false;
    if (!attr_set) {
        cudaFuncSetAttribute(hmma_gemm, cudaFuncAttributeMaxDynamicSharedMemorySize, SMEM_TOT);
        cudaFuncSetAttribute(hmma_gemm_qkv, cudaFuncAttributeMaxDynamicSharedMemorySize, SMEM_TOT);
        cudaFuncSetAttribute(attn_mma, cudaFuncAttributeMaxDynamicSharedMemorySize, SMEM_ATTN);
        attr_set = true;
    }

    __half *ahi, *qhi, *ehi, *wq, *wt, *wo, *kv;
    float* pbuf;
    cudaGetSymbolAddress((void**)&ahi, g_ahi);
    cudaGetSymbolAddress((void**)&qhi, g_qhi);
    cudaGetSymbolAddress((void**)&ehi, g_ehi);
    cudaGetSymbolAddress((void**)&wq,  g_wqT);
    cudaGetSymbolAddress((void**)&wt,  g_wT);
    cudaGetSymbolAddress((void**)&wo,  g_woutT);
    cudaGetSymbolAddress((void**)&kv,  g_kv);
    cudaGetSymbolAddress((void**)&pbuf, g_part);

    const int M_big = NB * SQ;  // 16384
    const long WSLAB = (long)HIDDEN * CROSS;

    // 1) activation fp16 converts
    {
        int n4 = M_big * HIDDEN / 4;
        split_hi_kernel<<<(n4 + 255) / 256, 256>>>(hidden, ahi, n4);
    }
    {
        int n4 = NB * ENC * CROSS / 4;
        split_hi_kernel<<<(n4 + 255) / 256, 256>>>(enc, ehi, n4);
    }

    // 2) all weight transposes in one launch
    {
        TSArgs t;
        t.src[0] = Wq;    t.dst[0] = wq;             t.K[0] = HIDDEN;
        t.src[1] = Wk;    t.dst[1] = wt + 0 * WSLAB; t.K[1] = CROSS;
        t.src[2] = Wv;    t.dst[2] = wt + 1 * WSLAB; t.K[2] = CROSS;
        t.src[3] = Wk_ip; t.dst[3] = wt + 2 * WSLAB; t.K[3] = CROSS;
        t.src[4] = Wv_ip; t.dst[4] = wt + 3 * WSLAB; t.K[4] = CROSS;
        t.src[5] = Wout;  t.dst[5] = wo;             t.K[5] = HIDDEN;
        transpose_all<<<dim3(HIDDEN / 32, CROSS / 32, 6), dim3(32, 8)>>>(t);
    }

    // 3) merged Q projection + packed split-K kv projections (1920 CTAs)
    {
        QKVArgs a;
        a.ahi = ahi; a.ehi = ehi;
        a.wq = wq; a.wt = wt;
        a.qhi = qhi; a.pbuf = pbuf;
        hmma_gemm_qkv<<<1920, 256, SMEM_TOT>>>(a);
    }

    // 4) reduce split-K partials -> kv fp16
    {
        long n4 = PART_STRIDE / 4;
        reduce_split_kv<<<(int)((n4 + 255) / 256), 256>>>(pbuf, kv);
    }

    // 5) HMMA attention -> hs fp16 (reuses g_ahi)
    attn_mma<<<dim3(SQ / 128, NHEADS, NB), 256, SMEM_ATTN>>>(qhi, kv, ahi);

    // 6) out = hs @ Wout + b_out + residual (fp32)
    {
        GemmArgs a = {ahi, wo, out, HIDDEN, HIDDEN, b_out, hidden};
        hmma_gemm<<<dim3(HIDDEN / 128, M_big / 128, 1), 256, SMEM_TOT>>>(a);
    }
}